// round 3
// baseline (speedup 1.0000x reference)
#include <cuda_runtime.h>
#include <math.h>

#define BN 8192
#define CN 1000
#define DN 128
#define NSPLIT 16
#define TI 128
#define TJ 128
#define LDS_ (DN + 4)   // 132 floats: pad for bank spread, keeps float4 alignment

// ---------------- scratch (static device memory; no runtime allocation) ----
__device__ float g_featn[BN * DN];
__device__ float g_meansn[CN * DN];
__device__ float g_XX[BN];
__device__ float g_YY[CN];
__device__ int   g_lab[BN];
__device__ float g_pb[NSPLIT * BN];   // partial exp-sum (bottom)
__device__ float g_pp[NSPLIT * BN];   // partial positive sim sum
__device__ int   g_pc[NSPLIT * BN];   // partial positive count
__device__ float g_ce[BN];
__device__ float g_margin[BN];
__device__ float g_peri[BN];
__device__ float g_valid[BN];

// ---------------- prep: normalize feat; labels are int32 on device ---------
__global__ void prep_feat_kernel(const float* __restrict__ feat,
                                 const int* __restrict__ labels) {
    int row = blockIdx.x * 8 + threadIdx.y;   // blockDim = (32,8)
    int lane = threadIdx.x;
    float4 v = ((const float4*)(feat + (size_t)row * DN))[lane];
    float ss = v.x * v.x + v.y * v.y + v.z * v.z + v.w * v.w;
    #pragma unroll
    for (int d = 16; d; d >>= 1) ss += __shfl_xor_sync(0xffffffffu, ss, d);
    float n = fmaxf(sqrtf(ss), 1e-12f);
    float inv = 1.0f / n;
    float4 o = make_float4(v.x * inv, v.y * inv, v.z * inv, v.w * inv);
    ((float4*)(g_featn + (size_t)row * DN))[lane] = o;
    if (lane == 0) {
        g_XX[row] = ss * inv * inv;
        g_lab[row] = labels[row];
    }
}

__global__ void prep_means_kernel(const float* __restrict__ means) {
    int row = blockIdx.x * 8 + threadIdx.y;   // 125 blocks * 8 = 1000 exact
    int lane = threadIdx.x;
    float4 v = ((const float4*)(means + (size_t)row * DN))[lane];
    float ss = v.x * v.x + v.y * v.y + v.z * v.z + v.w * v.w;
    #pragma unroll
    for (int d = 16; d; d >>= 1) ss += __shfl_xor_sync(0xffffffffu, ss, d);
    float n = fmaxf(sqrtf(ss), 1e-12f);
    float inv = 1.0f / n;
    float4 o = make_float4(v.x * inv, v.y * inv, v.z * inv, v.w * inv);
    ((float4*)(g_meansn + (size_t)row * DN))[lane] = o;
    if (lane == 0) g_YY[row] = ss;    // YY uses UNnormalized means
}

// ---------------- nsd GEMM: out[b,c] = -0.5*(XX - 2*featn.means + YY) ------
__global__ void nsd_kernel(const float* __restrict__ means,
                           float* __restrict__ out) {
    extern __shared__ float sm[];
    float* As = sm;                 // [TI][LDS_]
    float* Bs = sm + TI * LDS_;     // [TJ][LDS_]
    int ib = blockIdx.x * TI;
    int cb = blockIdx.y * TJ;
    int tid = threadIdx.x;
    int tx = tid & 15, ty = tid >> 4;
    int r = tid >> 5, q = tid & 31;

    #pragma unroll
    for (int it = 0; it < TI; it += 8)
        *(float4*)(As + (it + r) * LDS_ + q * 4) =
            *(const float4*)(g_featn + (size_t)(ib + it + r) * DN + q * 4);
    #pragma unroll
    for (int it = 0; it < TJ; it += 8) {
        int c = cb + it + r;
        float4 v = make_float4(0.f, 0.f, 0.f, 0.f);
        if (c < CN) v = *(const float4*)(means + (size_t)c * DN + q * 4);
        *(float4*)(Bs + (it + r) * LDS_ + q * 4) = v;
    }
    __syncthreads();

    float acc[8][8];
    #pragma unroll
    for (int ii = 0; ii < 8; ii++)
        #pragma unroll
        for (int jj = 0; jj < 8; jj++) acc[ii][jj] = 0.f;

    #pragma unroll 2
    for (int k = 0; k < DN; k += 4) {
        float4 av[8], bv[8];
        #pragma unroll
        for (int ii = 0; ii < 8; ii++) av[ii] = *(float4*)(As + (ty + ii * 16) * LDS_ + k);
        #pragma unroll
        for (int jj = 0; jj < 8; jj++) bv[jj] = *(float4*)(Bs + (tx + jj * 16) * LDS_ + k);
        #pragma unroll
        for (int ii = 0; ii < 8; ii++)
            #pragma unroll
            for (int jj = 0; jj < 8; jj++) {
                acc[ii][jj] += av[ii].x * bv[jj].x;
                acc[ii][jj] += av[ii].y * bv[jj].y;
                acc[ii][jj] += av[ii].z * bv[jj].z;
                acc[ii][jj] += av[ii].w * bv[jj].w;
            }
    }

    #pragma unroll
    for (int ii = 0; ii < 8; ii++) {
        int i = ib + ty + ii * 16;
        float xx = g_XX[i];
        #pragma unroll
        for (int jj = 0; jj < 8; jj++) {
            int c = cb + tx + jj * 16;
            if (c < CN)
                out[(size_t)i * CN + c] = -0.5f * (xx - 2.0f * acc[ii][jj] + g_YY[c]);
        }
    }
}

// ---------------- CE (log-softmax with margin) + per-sample margin ---------
__global__ void ce_kernel(const float* __restrict__ nsd) {
    int i = blockIdx.x;
    int t = threadIdx.x;        // 256
    __shared__ float red[256];
    __shared__ float s_vlab;
    int lab = g_lab[i];

    float v[4];
    float m = -1e30f;
    #pragma unroll
    for (int p = 0; p < 4; p++) {
        int c = t + p * 256;
        float x = -1e30f;
        if (c < CN) {
            x = nsd[(size_t)i * CN + c];
            if (c == lab) { x *= 1.5f; s_vlab = x; }   // K = 1 + ALPHA on true class
        }
        v[p] = x;
        m = fmaxf(m, x);
    }
    red[t] = m; __syncthreads();
    for (int d = 128; d; d >>= 1) { if (t < d) red[t] = fmaxf(red[t], red[t + d]); __syncthreads(); }
    m = red[0]; __syncthreads();

    float e = 0.f;
    #pragma unroll
    for (int p = 0; p < 4; p++)
        if (v[p] > -1e29f) e += __expf(v[p] - m);
    red[t] = e; __syncthreads();
    for (int d = 128; d; d >>= 1) { if (t < d) red[t] += red[t + d]; __syncthreads(); }
    if (t == 0) g_ce[i] = -(s_vlab - m - logf(red[0]));
    __syncthreads();

    // margin: ||featn[i] - meansn[lab]||^2
    float ms = 0.f;
    if (t < DN) {
        float d0 = g_featn[(size_t)i * DN + t] - g_meansn[(size_t)lab * DN + t];
        ms = d0 * d0;
    }
    red[t] = ms; __syncthreads();
    for (int d = 128; d; d >>= 1) { if (t < d) red[t] += red[t + d]; __syncthreads(); }
    if (t == 0) g_margin[i] = red[0];
}

// ---------------- SCL fused GEMM + row reduction ---------------------------
__global__ void scl_kernel() {
    extern __shared__ float sm[];
    float* As = sm;                         // [TI][LDS_]
    float* Bs = sm + TI * LDS_;             // [TJ][LDS_]
    int*   jl = (int*)(sm + 2 * TI * LDS_); // [TJ]

    int ib = blockIdx.x * TI;
    int split = blockIdx.y;
    int jbase = split * (BN / NSPLIT);      // 512 per split
    int tid = threadIdx.x;
    int tx = tid & 15, ty = tid >> 4;
    int r = tid >> 5, q = tid & 31;

    #pragma unroll
    for (int it = 0; it < TI; it += 8)
        *(float4*)(As + (it + r) * LDS_ + q * 4) =
            *(const float4*)(g_featn + (size_t)(ib + it + r) * DN + q * 4);

    int li[8];
    #pragma unroll
    for (int ii = 0; ii < 8; ii++) li[ii] = g_lab[ib + ty + ii * 16];

    float pb[8], pp[8];
    int pc[8];
    #pragma unroll
    for (int ii = 0; ii < 8; ii++) { pb[ii] = 0.f; pp[ii] = 0.f; pc[ii] = 0; }

    const float invT = 1.0f / 0.3f;

    for (int jt = 0; jt < (BN / NSPLIT) / TJ; jt++) {   // 4 j-tiles per split
        int jb = jbase + jt * TJ;
        __syncthreads();
        #pragma unroll
        for (int it = 0; it < TJ; it += 8)
            *(float4*)(Bs + (it + r) * LDS_ + q * 4) =
                *(const float4*)(g_featn + (size_t)(jb + it + r) * DN + q * 4);
        if (tid < TJ) jl[tid] = g_lab[jb + tid];
        __syncthreads();

        float acc[8][8];
        #pragma unroll
        for (int ii = 0; ii < 8; ii++)
            #pragma unroll
            for (int jj = 0; jj < 8; jj++) acc[ii][jj] = 0.f;

        #pragma unroll 2
        for (int k = 0; k < DN; k += 4) {
            float4 av[8], bv[8];
            #pragma unroll
            for (int ii = 0; ii < 8; ii++) av[ii] = *(float4*)(As + (ty + ii * 16) * LDS_ + k);
            #pragma unroll
            for (int jj = 0; jj < 8; jj++) bv[jj] = *(float4*)(Bs + (tx + jj * 16) * LDS_ + k);
            #pragma unroll
            for (int ii = 0; ii < 8; ii++)
                #pragma unroll
                for (int jj = 0; jj < 8; jj++) {
                    acc[ii][jj] += av[ii].x * bv[jj].x;
                    acc[ii][jj] += av[ii].y * bv[jj].y;
                    acc[ii][jj] += av[ii].z * bv[jj].z;
                    acc[ii][jj] += av[ii].w * bv[jj].w;
                }
        }

        #pragma unroll
        for (int ii = 0; ii < 8; ii++) {
            int ig = ib + ty + ii * 16;
            #pragma unroll
            for (int jj = 0; jj < 8; jj++) {
                int jloc = tx + jj * 16;
                int jg = jb + jloc;
                float s = acc[ii][jj] * invT;
                if (jg != ig) {
                    pb[ii] += __expf(s);
                    if (jl[jloc] == li[ii]) { pp[ii] += s; pc[ii]++; }
                }
            }
        }
    }

    // reduce across the 16 tx lanes that share each row
    #pragma unroll
    for (int ii = 0; ii < 8; ii++) {
        float b = pb[ii], p = pp[ii];
        int c = pc[ii];
        #pragma unroll
        for (int d = 8; d; d >>= 1) {
            b += __shfl_down_sync(0xffffffffu, b, d, 16);
            p += __shfl_down_sync(0xffffffffu, p, d, 16);
            c += __shfl_down_sync(0xffffffffu, c, d, 16);
        }
        if (tx == 0) {
            int i = ib + ty + ii * 16;
            g_pb[split * BN + i] = b;
            g_pp[split * BN + i] = p;
            g_pc[split * BN + i] = c;
        }
    }
}

// ---------------- deterministic split combine ------------------------------
__global__ void combine_kernel() {
    int i = blockIdx.x * 256 + threadIdx.x;
    float b = 0.f, p = 0.f;
    int c = 0;
    #pragma unroll
    for (int s = 0; s < NSPLIT; s++) {
        b += g_pb[s * BN + i];
        p += g_pp[s * BN + i];
        c += g_pc[s * BN + i];
    }
    bool valid = (c > 0);
    g_peri[i]  = valid ? (p / (float)c - logf(b)) : 0.f;
    g_valid[i] = valid ? 1.f : 0.f;
}

// ---------------- final scalar ---------------------------------------------
__global__ void final_kernel(float* __restrict__ out, long long scalar_idx) {
    int t = threadIdx.x;
    float sp = 0.f, sv = 0.f, sc = 0.f, smg = 0.f;
    for (int i = t; i < BN; i += 256) {
        sp += g_peri[i];
        sv += g_valid[i];
        sc += g_ce[i];
        smg += g_margin[i];
    }
    __shared__ float r0[256], r1[256], r2[256], r3[256];
    r0[t] = sp; r1[t] = sv; r2[t] = sc; r3[t] = smg;
    __syncthreads();
    for (int d = 128; d; d >>= 1) {
        if (t < d) { r0[t] += r0[t+d]; r1[t] += r1[t+d]; r2[t] += r2[t+d]; r3[t] += r3[t+d]; }
        __syncthreads();
    }
    if (t == 0) {
        float scl = -r0[0] / fmaxf(r1[0], 1.f);
        float ce  = r2[0] / (float)BN;
        float lm  = r3[0] / (2.f * (float)BN);
        out[scalar_idx] = 0.9f * ce + 0.1f * scl + 0.5f * lm;
    }
}

// ---------------- launch ----------------------------------------------------
extern "C" void kernel_launch(void* const* d_in, const int* in_sizes, int n_in,
                              void* d_out, int out_size) {
    const float* feat   = (const float*)d_in[0];
    const int*   labels = (const int*)d_in[1];     // int64 ref -> int32 on device
    const float* means  = (const float*)d_in[2];
    float* out = (float*)d_out;

    int smem = 2 * TI * LDS_ * (int)sizeof(float) + TJ * (int)sizeof(int); // 135680 B
    cudaFuncSetAttribute(nsd_kernel, cudaFuncAttributeMaxDynamicSharedMemorySize, smem);
    cudaFuncSetAttribute(scl_kernel, cudaFuncAttributeMaxDynamicSharedMemorySize, smem);

    prep_feat_kernel<<<BN / 8, dim3(32, 8)>>>(feat, labels);
    prep_means_kernel<<<CN / 8, dim3(32, 8)>>>(means);
    nsd_kernel<<<dim3(BN / TI, (CN + TJ - 1) / TJ), 256, smem>>>(means, out);
    ce_kernel<<<BN, 256>>>(out);
    scl_kernel<<<dim3(BN / TI, NSPLIT), 256, smem>>>();
    combine_kernel<<<BN / 256, 256>>>();
    final_kernel<<<1, 256>>>(out, (long long)out_size - 1);
}

// round 6
// speedup vs baseline: 2.3126x; 2.3126x over previous
#include <cuda_runtime.h>
#include <cuda_bf16.h>
#include <math.h>
#include <cstdint>

#define BN 8192
#define CN 1000
#define DN 128
#define TSPLIT 8
#define TI 128
#define TJ 128
#define LDS_ (DN + 4)
#define BSTRIDE 144   // bytes per bf16 tile row in smem (128 data + 16 pad): conflict-free ldmatrix

// ---------------- scratch ---------------------------------------------------
__device__ float g_featn[BN * DN];
__device__ __nv_bfloat16 g_featb[BN * DN];
__device__ float g_meansn[CN * DN];
__device__ float g_XX[BN];
__device__ float g_YY[CN];
__device__ int   g_lab[BN];
__device__ float g_pb[TSPLIT * BN];
__device__ float g_pp[TSPLIT * BN];
__device__ int   g_pc[TSPLIT * BN];
__device__ float g_ce[BN];
__device__ float g_margin[BN];
__device__ float g_peri[BN];
__device__ float g_valid[BN];

__device__ __forceinline__ uint32_t smem_u32(const void* p) {
    uint32_t a;
    asm("{ .reg .u64 t; cvta.to.shared.u64 t, %1; cvt.u32.u64 %0, t; }" : "=r"(a) : "l"(p));
    return a;
}

// ---------------- prep -------------------------------------------------------
__global__ void prep_feat_kernel(const float* __restrict__ feat,
                                 const int* __restrict__ labels) {
    int row = blockIdx.x * 8 + threadIdx.y;
    int lane = threadIdx.x;
    float4 v = ((const float4*)(feat + (size_t)row * DN))[lane];
    float ss = v.x * v.x + v.y * v.y + v.z * v.z + v.w * v.w;
    #pragma unroll
    for (int d = 16; d; d >>= 1) ss += __shfl_xor_sync(0xffffffffu, ss, d);
    float inv = 1.0f / fmaxf(sqrtf(ss), 1e-12f);
    float4 o = make_float4(v.x * inv, v.y * inv, v.z * inv, v.w * inv);
    ((float4*)(g_featn + (size_t)row * DN))[lane] = o;
    __nv_bfloat162 b0 = __floats2bfloat162_rn(o.x, o.y);
    __nv_bfloat162 b1 = __floats2bfloat162_rn(o.z, o.w);
    uint2 pk = make_uint2(*(uint32_t*)&b0, *(uint32_t*)&b1);
    ((uint2*)(g_featb + (size_t)row * DN))[lane] = pk;
    if (lane == 0) {
        g_XX[row] = ss * inv * inv;
        g_lab[row] = labels[row];
    }
}

__global__ void prep_means_kernel(const float* __restrict__ means) {
    int row = blockIdx.x * 8 + threadIdx.y;
    int lane = threadIdx.x;
    float4 v = ((const float4*)(means + (size_t)row * DN))[lane];
    float ss = v.x * v.x + v.y * v.y + v.z * v.z + v.w * v.w;
    #pragma unroll
    for (int d = 16; d; d >>= 1) ss += __shfl_xor_sync(0xffffffffu, ss, d);
    float inv = 1.0f / fmaxf(sqrtf(ss), 1e-12f);
    float4 o = make_float4(v.x * inv, v.y * inv, v.z * inv, v.w * inv);
    ((float4*)(g_meansn + (size_t)row * DN))[lane] = o;
    if (lane == 0) g_YY[row] = ss;
}

// ---------------- nsd GEMM (fp32, exact output) -----------------------------
__global__ void nsd_kernel(const float* __restrict__ means,
                           float* __restrict__ out) {
    extern __shared__ float sm[];
    float* As = sm;
    float* Bs = sm + TI * LDS_;
    int ib = blockIdx.x * TI;
    int cb = blockIdx.y * TJ;
    int tid = threadIdx.x;
    int tx = tid & 15, ty = tid >> 4;
    int r = tid >> 5, q = tid & 31;

    #pragma unroll
    for (int it = 0; it < TI; it += 8)
        *(float4*)(As + (it + r) * LDS_ + q * 4) =
            *(const float4*)(g_featn + (size_t)(ib + it + r) * DN + q * 4);
    #pragma unroll
    for (int it = 0; it < TJ; it += 8) {
        int c = cb + it + r;
        float4 v = make_float4(0.f, 0.f, 0.f, 0.f);
        if (c < CN) v = *(const float4*)(means + (size_t)c * DN + q * 4);
        *(float4*)(Bs + (it + r) * LDS_ + q * 4) = v;
    }
    __syncthreads();

    float acc[8][8];
    #pragma unroll
    for (int ii = 0; ii < 8; ii++)
        #pragma unroll
        for (int jj = 0; jj < 8; jj++) acc[ii][jj] = 0.f;

    #pragma unroll 2
    for (int k = 0; k < DN; k += 4) {
        float4 av[8], bv[8];
        #pragma unroll
        for (int ii = 0; ii < 8; ii++) av[ii] = *(float4*)(As + (ty + ii * 16) * LDS_ + k);
        #pragma unroll
        for (int jj = 0; jj < 8; jj++) bv[jj] = *(float4*)(Bs + (tx + jj * 16) * LDS_ + k);
        #pragma unroll
        for (int ii = 0; ii < 8; ii++)
            #pragma unroll
            for (int jj = 0; jj < 8; jj++) {
                acc[ii][jj] += av[ii].x * bv[jj].x;
                acc[ii][jj] += av[ii].y * bv[jj].y;
                acc[ii][jj] += av[ii].z * bv[jj].z;
                acc[ii][jj] += av[ii].w * bv[jj].w;
            }
    }

    #pragma unroll
    for (int ii = 0; ii < 8; ii++) {
        int i = ib + ty + ii * 16;
        float xx = g_XX[i];
        #pragma unroll
        for (int jj = 0; jj < 8; jj++) {
            int c = cb + tx + jj * 16;
            if (c < CN)
                out[(size_t)i * CN + c] = -0.5f * (xx - 2.0f * acc[ii][jj] + g_YY[c]);
        }
    }
}

// ---------------- CE + margin ------------------------------------------------
__global__ void ce_kernel(const float* __restrict__ nsd) {
    int i = blockIdx.x;
    int t = threadIdx.x;
    __shared__ float red[256];
    __shared__ float s_vlab;
    int lab = g_lab[i];

    float v[4];
    float m = -1e30f;
    #pragma unroll
    for (int p = 0; p < 4; p++) {
        int c = t + p * 256;
        float x = -1e30f;
        if (c < CN) {
            x = nsd[(size_t)i * CN + c];
            if (c == lab) { x *= 1.5f; s_vlab = x; }
        }
        v[p] = x;
        m = fmaxf(m, x);
    }
    red[t] = m; __syncthreads();
    for (int d = 128; d; d >>= 1) { if (t < d) red[t] = fmaxf(red[t], red[t + d]); __syncthreads(); }
    m = red[0]; __syncthreads();

    float e = 0.f;
    #pragma unroll
    for (int p = 0; p < 4; p++)
        if (v[p] > -1e29f) e += __expf(v[p] - m);
    red[t] = e; __syncthreads();
    for (int d = 128; d; d >>= 1) { if (t < d) red[t] += red[t + d]; __syncthreads(); }
    if (t == 0) g_ce[i] = -(s_vlab - m - logf(red[0]));
    __syncthreads();

    float ms = 0.f;
    if (t < DN) {
        float d0 = g_featn[(size_t)i * DN + t] - g_meansn[(size_t)lab * DN + t];
        ms = d0 * d0;
    }
    red[t] = ms; __syncthreads();
    for (int d = 128; d; d >>= 1) { if (t < d) red[t] += red[t + d]; __syncthreads(); }
    if (t == 0) g_margin[i] = red[0];
}

// ---------------- SCL: mma.sync bf16 fused GEMM + row reduction --------------
__global__ void __launch_bounds__(256) scl_mma_kernel() {
    __shared__ __align__(16) char smA[128 * BSTRIDE];
    __shared__ __align__(16) char smB[128 * BSTRIDE];
    __shared__ int jl[128];

    int tid = threadIdx.x;
    int w = tid >> 5;
    int l = tid & 31;
    int ib = blockIdx.x * 128;
    int split = blockIdx.y;

    // ---- load A tile (128 rows x 128 bf16) into padded smem ----
    {
        int r = tid >> 1, h = tid & 1;
        const uint4* src = (const uint4*)(g_featb + (size_t)(ib + r) * DN + h * 64);
        uint4* dst = (uint4*)(smA + r * BSTRIDE + h * 128);
        #pragma unroll
        for (int i = 0; i < 8; i++) dst[i] = src[i];
    }
    __syncthreads();

    // ---- A fragments for this warp's 16 rows, all 8 k-steps (stay in regs) ----
    uint32_t a[8][4];
    {
        uint32_t base = smem_u32(smA);
        uint32_t row = 16 * w + (l & 15);
        uint32_t koff = 8 * (l >> 4);   // halves
        #pragma unroll
        for (int ks = 0; ks < 8; ks++) {
            uint32_t addr = base + row * BSTRIDE + (16 * ks + koff) * 2;
            asm volatile("ldmatrix.sync.aligned.m8n8.x4.shared.b16 {%0,%1,%2,%3}, [%4];"
                         : "=r"(a[ks][0]), "=r"(a[ks][1]), "=r"(a[ks][2]), "=r"(a[ks][3])
                         : "r"(addr));
        }
    }

    int r0 = 16 * w + (l >> 2), r1 = r0 + 8;
    int ig0 = ib + r0, ig1 = ib + r1;
    int lab0 = g_lab[ig0], lab1 = g_lab[ig1];

    const float invT = 1.0f / 0.3f;
    float sB0 = 0.f, sB1 = 0.f, sP0 = 0.f, sP1 = 0.f;
    int sC0 = 0, sC1 = 0;

    uint32_t bbase = smem_u32(smB);
    uint32_t brow = (l & 7);
    uint32_t bkoff = 8 * (l >> 3);   // halves

    for (int jt = 0; jt < 64 / TSPLIT; jt++) {
        int jb = (split * (64 / TSPLIT) + jt) * 128;

        __syncthreads();   // previous tile's B fully consumed
        {
            int r = tid >> 1, h = tid & 1;
            const uint4* src = (const uint4*)(g_featb + (size_t)(jb + r) * DN + h * 64);
            uint4* dst = (uint4*)(smB + r * BSTRIDE + h * 128);
            #pragma unroll
            for (int i = 0; i < 8; i++) dst[i] = src[i];
            if (tid < 128) jl[tid] = g_lab[jb + tid];
        }
        __syncthreads();

        #pragma unroll
        for (int nb = 0; nb < 16; nb++) {
            float d0 = 0.f, d1 = 0.f, d2 = 0.f, d3 = 0.f;
            #pragma unroll
            for (int kp = 0; kp < 4; kp++) {
                uint32_t b0, b1, b2, b3;
                uint32_t addr = bbase + (nb * 8 + brow) * BSTRIDE + (32 * kp + bkoff) * 2;
                asm volatile("ldmatrix.sync.aligned.m8n8.x4.shared.b16 {%0,%1,%2,%3}, [%4];"
                             : "=r"(b0), "=r"(b1), "=r"(b2), "=r"(b3) : "r"(addr));
                asm volatile(
                    "mma.sync.aligned.m16n8k16.row.col.f32.bf16.bf16.f32 "
                    "{%0,%1,%2,%3}, {%4,%5,%6,%7}, {%8,%9}, {%0,%1,%2,%3};"
                    : "+f"(d0), "+f"(d1), "+f"(d2), "+f"(d3)
                    : "r"(a[2 * kp][0]), "r"(a[2 * kp][1]), "r"(a[2 * kp][2]), "r"(a[2 * kp][3]),
                      "r"(b0), "r"(b1));
                asm volatile(
                    "mma.sync.aligned.m16n8k16.row.col.f32.bf16.bf16.f32 "
                    "{%0,%1,%2,%3}, {%4,%5,%6,%7}, {%8,%9}, {%0,%1,%2,%3};"
                    : "+f"(d0), "+f"(d1), "+f"(d2), "+f"(d3)
                    : "r"(a[2 * kp + 1][0]), "r"(a[2 * kp + 1][1]), "r"(a[2 * kp + 1][2]), "r"(a[2 * kp + 1][3]),
                      "r"(b2), "r"(b3));
            }
            // epilogue: c0=(r0,col) c1=(r0,col+1) c2=(r1,col) c3=(r1,col+1)
            int col = nb * 8 + 2 * (l & 3);
            int jg0 = jb + col, jg1 = jg0 + 1;
            int jl0 = jl[col], jl1 = jl[col + 1];
            float s0 = d0 * invT, s1 = d1 * invT, s2 = d2 * invT, s3 = d3 * invT;
            if (jg0 != ig0) { sB0 += __expf(s0); if (jl0 == lab0) { sP0 += s0; sC0++; } }
            if (jg1 != ig0) { sB0 += __expf(s1); if (jl1 == lab0) { sP0 += s1; sC0++; } }
            if (jg0 != ig1) { sB1 += __expf(s2); if (jl0 == lab1) { sP1 += s2; sC1++; } }
            if (jg1 != ig1) { sB1 += __expf(s3); if (jl1 == lab1) { sP1 += s3; sC1++; } }
        }
    }

    // deterministic reduce across the 4 lanes sharing each row (width-4 segments)
    #pragma unroll
    for (int d = 2; d; d >>= 1) {
        sB0 += __shfl_down_sync(0xffffffffu, sB0, d, 4);
        sB1 += __shfl_down_sync(0xffffffffu, sB1, d, 4);
        sP0 += __shfl_down_sync(0xffffffffu, sP0, d, 4);
        sP1 += __shfl_down_sync(0xffffffffu, sP1, d, 4);
        sC0 += __shfl_down_sync(0xffffffffu, sC0, d, 4);
        sC1 += __shfl_down_sync(0xffffffffu, sC1, d, 4);
    }
    if ((l & 3) == 0) {
        g_pb[split * BN + ig0] = sB0;
        g_pp[split * BN + ig0] = sP0;
        g_pc[split * BN + ig0] = sC0;
        g_pb[split * BN + ig1] = sB1;
        g_pp[split * BN + ig1] = sP1;
        g_pc[split * BN + ig1] = sC1;
    }
}

// ---------------- combine + final --------------------------------------------
__global__ void combine_kernel() {
    int i = blockIdx.x * 256 + threadIdx.x;
    float b = 0.f, p = 0.f;
    int c = 0;
    #pragma unroll
    for (int s = 0; s < TSPLIT; s++) {
        b += g_pb[s * BN + i];
        p += g_pp[s * BN + i];
        c += g_pc[s * BN + i];
    }
    bool valid = (c > 0);
    g_peri[i]  = valid ? (p / (float)c - logf(b)) : 0.f;
    g_valid[i] = valid ? 1.f : 0.f;
}

__global__ void final_kernel(float* __restrict__ out, long long scalar_idx) {
    int t = threadIdx.x;
    float sp = 0.f, sv = 0.f, sc = 0.f, smg = 0.f;
    for (int i = t; i < BN; i += 256) {
        sp += g_peri[i];
        sv += g_valid[i];
        sc += g_ce[i];
        smg += g_margin[i];
    }
    __shared__ float r0[256], r1[256], r2[256], r3[256];
    r0[t] = sp; r1[t] = sv; r2[t] = sc; r3[t] = smg;
    __syncthreads();
    for (int d = 128; d; d >>= 1) {
        if (t < d) { r0[t] += r0[t+d]; r1[t] += r1[t+d]; r2[t] += r2[t+d]; r3[t] += r3[t+d]; }
        __syncthreads();
    }
    if (t == 0) {
        float scl = -r0[0] / fmaxf(r1[0], 1.f);
        float ce  = r2[0] / (float)BN;
        float lm  = r3[0] / (2.f * (float)BN);
        out[scalar_idx] = 0.9f * ce + 0.1f * scl + 0.5f * lm;
    }
}

// ---------------- launch ------------------------------------------------------
extern "C" void kernel_launch(void* const* d_in, const int* in_sizes, int n_in,
                              void* d_out, int out_size) {
    const float* feat   = (const float*)d_in[0];
    const int*   labels = (const int*)d_in[1];
    const float* means  = (const float*)d_in[2];
    float* out = (float*)d_out;

    int smem_nsd = 2 * TI * LDS_ * (int)sizeof(float);
    cudaFuncSetAttribute(nsd_kernel, cudaFuncAttributeMaxDynamicSharedMemorySize, smem_nsd);

    prep_feat_kernel<<<BN / 8, dim3(32, 8)>>>(feat, labels);
    prep_means_kernel<<<CN / 8, dim3(32, 8)>>>(means);
    nsd_kernel<<<dim3(BN / TI, (CN + TJ - 1) / TJ), 256, smem_nsd>>>(means, out);
    ce_kernel<<<BN, 256>>>(out);
    scl_mma_kernel<<<dim3(BN / 128, TSPLIT), 256>>>();
    combine_kernel<<<BN / 256, 256>>>();
    final_kernel<<<1, 256>>>(out, (long long)out_size - 1);
}

// round 7
// speedup vs baseline: 2.7660x; 1.1961x over previous
#include <cuda_runtime.h>
#include <cuda_bf16.h>
#include <math.h>
#include <cstdint>

#define BN 8192
#define CN 1000
#define DN 128
#define TSPLIT 8
#define TI 128
#define TJ 128
#define LDS_ (DN + 4)
#define BSTRIDE 144   // bytes per bf16 tile row in smem (128 data + 16 pad): conflict-free ldmatrix

// ---------------- scratch ---------------------------------------------------
__device__ float g_featn[BN * DN];
__device__ __nv_bfloat16 g_featb[BN * DN];
__device__ float g_meansn[CN * DN];
__device__ float g_XX[BN];
__device__ float g_YY[CN];
__device__ int   g_lab[BN];
__device__ float g_pb[TSPLIT * BN];
__device__ float g_pp[TSPLIT * BN];
__device__ int   g_pc[TSPLIT * BN];
__device__ float g_ce[BN];
__device__ float g_margin[BN];
__device__ float g_peri[BN];
__device__ float g_valid[BN];

__device__ __forceinline__ uint32_t smem_u32(const void* p) {
    uint32_t a;
    asm("{ .reg .u64 t; cvta.to.shared.u64 t, %1; cvt.u32.u64 %0, t; }" : "=r"(a) : "l"(p));
    return a;
}

// ---------------- prep -------------------------------------------------------
__global__ void prep_feat_kernel(const float* __restrict__ feat,
                                 const int* __restrict__ labels) {
    int row = blockIdx.x * 8 + threadIdx.y;
    int lane = threadIdx.x;
    float4 v = ((const float4*)(feat + (size_t)row * DN))[lane];
    float ss = v.x * v.x + v.y * v.y + v.z * v.z + v.w * v.w;
    #pragma unroll
    for (int d = 16; d; d >>= 1) ss += __shfl_xor_sync(0xffffffffu, ss, d);
    float inv = 1.0f / fmaxf(sqrtf(ss), 1e-12f);
    float4 o = make_float4(v.x * inv, v.y * inv, v.z * inv, v.w * inv);
    ((float4*)(g_featn + (size_t)row * DN))[lane] = o;
    __nv_bfloat162 b0 = __floats2bfloat162_rn(o.x, o.y);
    __nv_bfloat162 b1 = __floats2bfloat162_rn(o.z, o.w);
    uint2 pk = make_uint2(*(uint32_t*)&b0, *(uint32_t*)&b1);
    ((uint2*)(g_featb + (size_t)row * DN))[lane] = pk;
    if (lane == 0) {
        g_XX[row] = ss * inv * inv;
        g_lab[row] = labels[row];
    }
}

__global__ void prep_means_kernel(const float* __restrict__ means) {
    int row = blockIdx.x * 8 + threadIdx.y;
    int lane = threadIdx.x;
    float4 v = ((const float4*)(means + (size_t)row * DN))[lane];
    float ss = v.x * v.x + v.y * v.y + v.z * v.z + v.w * v.w;
    #pragma unroll
    for (int d = 16; d; d >>= 1) ss += __shfl_xor_sync(0xffffffffu, ss, d);
    float inv = 1.0f / fmaxf(sqrtf(ss), 1e-12f);
    float4 o = make_float4(v.x * inv, v.y * inv, v.z * inv, v.w * inv);
    ((float4*)(g_meansn + (size_t)row * DN))[lane] = o;
    if (lane == 0) g_YY[row] = ss;
}

// ---------------- nsd GEMM (fp32, exact output) -----------------------------
__global__ void nsd_kernel(const float* __restrict__ means,
                           float* __restrict__ out) {
    extern __shared__ float sm[];
    float* As = sm;
    float* Bs = sm + TI * LDS_;
    int ib = blockIdx.x * TI;
    int cb = blockIdx.y * TJ;
    int tid = threadIdx.x;
    int tx = tid & 15, ty = tid >> 4;
    int r = tid >> 5, q = tid & 31;

    #pragma unroll
    for (int it = 0; it < TI; it += 8)
        *(float4*)(As + (it + r) * LDS_ + q * 4) =
            *(const float4*)(g_featn + (size_t)(ib + it + r) * DN + q * 4);
    #pragma unroll
    for (int it = 0; it < TJ; it += 8) {
        int c = cb + it + r;
        float4 v = make_float4(0.f, 0.f, 0.f, 0.f);
        if (c < CN) v = *(const float4*)(means + (size_t)c * DN + q * 4);
        *(float4*)(Bs + (it + r) * LDS_ + q * 4) = v;
    }
    __syncthreads();

    float acc[8][8];
    #pragma unroll
    for (int ii = 0; ii < 8; ii++)
        #pragma unroll
        for (int jj = 0; jj < 8; jj++) acc[ii][jj] = 0.f;

    #pragma unroll 2
    for (int k = 0; k < DN; k += 4) {
        float4 av[8], bv[8];
        #pragma unroll
        for (int ii = 0; ii < 8; ii++) av[ii] = *(float4*)(As + (ty + ii * 16) * LDS_ + k);
        #pragma unroll
        for (int jj = 0; jj < 8; jj++) bv[jj] = *(float4*)(Bs + (tx + jj * 16) * LDS_ + k);
        #pragma unroll
        for (int ii = 0; ii < 8; ii++)
            #pragma unroll
            for (int jj = 0; jj < 8; jj++) {
                acc[ii][jj] += av[ii].x * bv[jj].x;
                acc[ii][jj] += av[ii].y * bv[jj].y;
                acc[ii][jj] += av[ii].z * bv[jj].z;
                acc[ii][jj] += av[ii].w * bv[jj].w;
            }
    }

    #pragma unroll
    for (int ii = 0; ii < 8; ii++) {
        int i = ib + ty + ii * 16;
        float xx = g_XX[i];
        #pragma unroll
        for (int jj = 0; jj < 8; jj++) {
            int c = cb + tx + jj * 16;
            if (c < CN)
                out[(size_t)i * CN + c] = -0.5f * (xx - 2.0f * acc[ii][jj] + g_YY[c]);
        }
    }
}

// ---------------- CE + margin: one warp per row ------------------------------
__global__ void __launch_bounds__(256) ce_kernel(const float* __restrict__ nsd) {
    int w = threadIdx.x >> 5, l = threadIdx.x & 31;
    int i = blockIdx.x * 8 + w;
    int lab = g_lab[i];
    const float4* row = (const float4*)(nsd + (size_t)i * CN);

    float4 v[8];
    float m = -1e30f, vlab = -1e30f;
    #pragma unroll
    for (int k = 0; k < 8; k++) {
        int idx = l + 32 * k;
        float4 x = make_float4(-1e30f, -1e30f, -1e30f, -1e30f);
        if (idx < 250) {
            x = row[idx];
            int c0 = idx * 4;
            if (lab == c0)     { x.x *= 1.5f; vlab = x.x; }
            if (lab == c0 + 1) { x.y *= 1.5f; vlab = x.y; }
            if (lab == c0 + 2) { x.z *= 1.5f; vlab = x.z; }
            if (lab == c0 + 3) { x.w *= 1.5f; vlab = x.w; }
            m = fmaxf(m, fmaxf(fmaxf(x.x, x.y), fmaxf(x.z, x.w)));
        }
        v[k] = x;
    }
    #pragma unroll
    for (int d = 16; d; d >>= 1) {
        m = fmaxf(m, __shfl_xor_sync(0xffffffffu, m, d));
        vlab = fmaxf(vlab, __shfl_xor_sync(0xffffffffu, vlab, d));
    }
    float e = 0.f;
    #pragma unroll
    for (int k = 0; k < 8; k++)
        e += __expf(v[k].x - m) + __expf(v[k].y - m)
           + __expf(v[k].z - m) + __expf(v[k].w - m);
    #pragma unroll
    for (int d = 16; d; d >>= 1) e += __shfl_xor_sync(0xffffffffu, e, d);
    if (l == 0) g_ce[i] = -(vlab - m - logf(e));

    // margin: ||featn[i] - meansn[lab]||^2, one float4 per lane (32*4 = 128)
    float4 f  = ((const float4*)(g_featn  + (size_t)i   * DN))[l];
    float4 mm = ((const float4*)(g_meansn + (size_t)lab * DN))[l];
    float dx = f.x - mm.x, dy = f.y - mm.y, dz = f.z - mm.z, dw = f.w - mm.w;
    float ms = dx * dx + dy * dy + dz * dz + dw * dw;
    #pragma unroll
    for (int d = 16; d; d >>= 1) ms += __shfl_xor_sync(0xffffffffu, ms, d);
    if (l == 0) g_margin[i] = ms;
}

// ---------------- SCL: mma.sync bf16 fused GEMM + row reduction --------------
__global__ void __launch_bounds__(256) scl_mma_kernel() {
    __shared__ __align__(16) char smA[128 * BSTRIDE];
    __shared__ __align__(16) char smB[128 * BSTRIDE];
    __shared__ int jl[128];

    int tid = threadIdx.x;
    int w = tid >> 5;
    int l = tid & 31;
    int ib = blockIdx.x * 128;
    int split = blockIdx.y;

    // ---- load A tile (128 rows x 128 bf16) into padded smem ----
    {
        int r = tid >> 1, h = tid & 1;
        const uint4* src = (const uint4*)(g_featb + (size_t)(ib + r) * DN + h * 64);
        uint4* dst = (uint4*)(smA + r * BSTRIDE + h * 128);
        #pragma unroll
        for (int i = 0; i < 8; i++) dst[i] = src[i];
    }
    __syncthreads();

    // ---- A fragments for this warp's 16 rows, all 8 k-steps (stay in regs) ----
    uint32_t a[8][4];
    {
        uint32_t base = smem_u32(smA);
        uint32_t row = 16 * w + (l & 15);
        uint32_t koff = 8 * (l >> 4);   // halves
        #pragma unroll
        for (int ks = 0; ks < 8; ks++) {
            uint32_t addr = base + row * BSTRIDE + (16 * ks + koff) * 2;
            asm volatile("ldmatrix.sync.aligned.m8n8.x4.shared.b16 {%0,%1,%2,%3}, [%4];"
                         : "=r"(a[ks][0]), "=r"(a[ks][1]), "=r"(a[ks][2]), "=r"(a[ks][3])
                         : "r"(addr));
        }
    }

    int r0 = 16 * w + (l >> 2), r1 = r0 + 8;
    int ig0 = ib + r0, ig1 = ib + r1;
    int lab0 = g_lab[ig0], lab1 = g_lab[ig1];

    const float invT = 1.0f / 0.3f;
    float sB0 = 0.f, sB1 = 0.f, sP0 = 0.f, sP1 = 0.f;
    int sC0 = 0, sC1 = 0;

    uint32_t bbase = smem_u32(smB);
    uint32_t brow = (l & 7);
    uint32_t bkoff = 8 * (l >> 3);   // halves

    for (int jt = 0; jt < 64 / TSPLIT; jt++) {
        int jb = (split * (64 / TSPLIT) + jt) * 128;

        __syncthreads();   // previous tile's B fully consumed
        {
            int r = tid >> 1, h = tid & 1;
            const uint4* src = (const uint4*)(g_featb + (size_t)(jb + r) * DN + h * 64);
            uint4* dst = (uint4*)(smB + r * BSTRIDE + h * 128);
            #pragma unroll
            for (int i = 0; i < 8; i++) dst[i] = src[i];
            if (tid < 128) jl[tid] = g_lab[jb + tid];
        }
        __syncthreads();

        #pragma unroll
        for (int nb = 0; nb < 16; nb++) {
            float d0 = 0.f, d1 = 0.f, d2 = 0.f, d3 = 0.f;
            #pragma unroll
            for (int kp = 0; kp < 4; kp++) {
                uint32_t b0, b1, b2, b3;
                uint32_t addr = bbase + (nb * 8 + brow) * BSTRIDE + (32 * kp + bkoff) * 2;
                asm volatile("ldmatrix.sync.aligned.m8n8.x4.shared.b16 {%0,%1,%2,%3}, [%4];"
                             : "=r"(b0), "=r"(b1), "=r"(b2), "=r"(b3) : "r"(addr));
                asm volatile(
                    "mma.sync.aligned.m16n8k16.row.col.f32.bf16.bf16.f32 "
                    "{%0,%1,%2,%3}, {%4,%5,%6,%7}, {%8,%9}, {%0,%1,%2,%3};"
                    : "+f"(d0), "+f"(d1), "+f"(d2), "+f"(d3)
                    : "r"(a[2 * kp][0]), "r"(a[2 * kp][1]), "r"(a[2 * kp][2]), "r"(a[2 * kp][3]),
                      "r"(b0), "r"(b1));
                asm volatile(
                    "mma.sync.aligned.m16n8k16.row.col.f32.bf16.bf16.f32 "
                    "{%0,%1,%2,%3}, {%4,%5,%6,%7}, {%8,%9}, {%0,%1,%2,%3};"
                    : "+f"(d0), "+f"(d1), "+f"(d2), "+f"(d3)
                    : "r"(a[2 * kp + 1][0]), "r"(a[2 * kp + 1][1]), "r"(a[2 * kp + 1][2]), "r"(a[2 * kp + 1][3]),
                      "r"(b2), "r"(b3));
            }
            // epilogue: c0=(r0,col) c1=(r0,col+1) c2=(r1,col) c3=(r1,col+1)
            int col = nb * 8 + 2 * (l & 3);
            int jg0 = jb + col, jg1 = jg0 + 1;
            int jl0 = jl[col], jl1 = jl[col + 1];
            float s0 = d0 * invT, s1 = d1 * invT, s2 = d2 * invT, s3 = d3 * invT;
            if (jg0 != ig0) { sB0 += __expf(s0); if (jl0 == lab0) { sP0 += s0; sC0++; } }
            if (jg1 != ig0) { sB0 += __expf(s1); if (jl1 == lab0) { sP0 += s1; sC0++; } }
            if (jg0 != ig1) { sB1 += __expf(s2); if (jl0 == lab1) { sP1 += s2; sC1++; } }
            if (jg1 != ig1) { sB1 += __expf(s3); if (jl1 == lab1) { sP1 += s3; sC1++; } }
        }
    }

    // deterministic reduce across the 4 lanes sharing each row (width-4 segments)
    #pragma unroll
    for (int d = 2; d; d >>= 1) {
        sB0 += __shfl_down_sync(0xffffffffu, sB0, d, 4);
        sB1 += __shfl_down_sync(0xffffffffu, sB1, d, 4);
        sP0 += __shfl_down_sync(0xffffffffu, sP0, d, 4);
        sP1 += __shfl_down_sync(0xffffffffu, sP1, d, 4);
        sC0 += __shfl_down_sync(0xffffffffu, sC0, d, 4);
        sC1 += __shfl_down_sync(0xffffffffu, sC1, d, 4);
    }
    if ((l & 3) == 0) {
        g_pb[split * BN + ig0] = sB0;
        g_pp[split * BN + ig0] = sP0;
        g_pc[split * BN + ig0] = sC0;
        g_pb[split * BN + ig1] = sB1;
        g_pp[split * BN + ig1] = sP1;
        g_pc[split * BN + ig1] = sC1;
    }
}

// ---------------- combine + final --------------------------------------------
__global__ void combine_kernel() {
    int i = blockIdx.x * 256 + threadIdx.x;
    float b = 0.f, p = 0.f;
    int c = 0;
    #pragma unroll
    for (int s = 0; s < TSPLIT; s++) {
        b += g_pb[s * BN + i];
        p += g_pp[s * BN + i];
        c += g_pc[s * BN + i];
    }
    bool valid = (c > 0);
    g_peri[i]  = valid ? (p / (float)c - logf(b)) : 0.f;
    g_valid[i] = valid ? 1.f : 0.f;
}

__global__ void final_kernel(float* __restrict__ out, long long scalar_idx) {
    int t = threadIdx.x;
    float sp = 0.f, sv = 0.f, sc = 0.f, smg = 0.f;
    for (int i = t; i < BN; i += 256) {
        sp += g_peri[i];
        sv += g_valid[i];
        sc += g_ce[i];
        smg += g_margin[i];
    }
    __shared__ float r0[256], r1[256], r2[256], r3[256];
    r0[t] = sp; r1[t] = sv; r2[t] = sc; r3[t] = smg;
    __syncthreads();
    for (int d = 128; d; d >>= 1) {
        if (t < d) { r0[t] += r0[t+d]; r1[t] += r1[t+d]; r2[t] += r2[t+d]; r3[t] += r3[t+d]; }
        __syncthreads();
    }
    if (t == 0) {
        float scl = -r0[0] / fmaxf(r1[0], 1.f);
        float ce  = r2[0] / (float)BN;
        float lm  = r3[0] / (2.f * (float)BN);
        out[scalar_idx] = 0.9f * ce + 0.1f * scl + 0.5f * lm;
    }
}

// ---------------- launch ------------------------------------------------------
extern "C" void kernel_launch(void* const* d_in, const int* in_sizes, int n_in,
                              void* d_out, int out_size) {
    const float* feat   = (const float*)d_in[0];
    const int*   labels = (const int*)d_in[1];
    const float* means  = (const float*)d_in[2];
    float* out = (float*)d_out;

    // lazy one-time creation of side stream + events (no device memory involved)
    static cudaStream_t sB = nullptr;
    static cudaEvent_t  eF = nullptr, eJ = nullptr;
    static int initTried = 0;
    if (!initTried) {
        initTried = 1;
        if (cudaStreamCreateWithFlags(&sB, cudaStreamNonBlocking) != cudaSuccess) sB = nullptr;
        if (sB) {
            if (cudaEventCreateWithFlags(&eF, cudaEventDisableTiming) != cudaSuccess) { eF = nullptr; }
            if (cudaEventCreateWithFlags(&eJ, cudaEventDisableTiming) != cudaSuccess) { eJ = nullptr; }
            if (!eF || !eJ) sB = nullptr;
        }
    }
    bool fork = (sB != nullptr);

    int smem_nsd = 2 * TI * LDS_ * (int)sizeof(float);
    cudaFuncSetAttribute(nsd_kernel, cudaFuncAttributeMaxDynamicSharedMemorySize, smem_nsd);

    prep_feat_kernel<<<BN / 8, dim3(32, 8)>>>(feat, labels);

    if (fork) {
        cudaEventRecord(eF, 0);
        cudaStreamWaitEvent(sB, eF, 0);
        scl_mma_kernel<<<dim3(BN / 128, TSPLIT), 256, 0, sB>>>();
        cudaEventRecord(eJ, sB);
    }

    prep_means_kernel<<<CN / 8, dim3(32, 8)>>>(means);
    nsd_kernel<<<dim3(BN / TI, (CN + TJ - 1) / TJ), 256, smem_nsd>>>(means, out);
    ce_kernel<<<BN / 8, 256>>>(out);

    if (fork) {
        cudaStreamWaitEvent(0, eJ, 0);
    } else {
        scl_mma_kernel<<<dim3(BN / 128, TSPLIT), 256>>>();
    }

    combine_kernel<<<BN / 256, 256>>>();
    final_kernel<<<1, 256>>>(out, (long long)out_size - 1);
}

// round 9
// speedup vs baseline: 3.2121x; 1.1613x over previous
#include <cuda_runtime.h>
#include <cuda_bf16.h>
#include <math.h>
#include <cstdint>

#define BN 8192
#define CN 1000
#define CPAD 1024
#define DN 128
#define TSPLIT 8
#define STRIDE 272                 // bytes per tile row: 256 data + 16 pad (conflict-free ldmatrix)
#define TILE_BYTES (128 * STRIDE)  // 34816
#define SMEM_TOT (2 * TILE_BYTES + 512)

// ---------------- scratch ---------------------------------------------------
__device__ float g_featn[BN * DN];
__device__ __nv_bfloat16 g_featbH[BN * DN];
__device__ __nv_bfloat16 g_featbL[BN * DN];
__device__ float g_meansn[CN * DN];
__device__ __nv_bfloat16 g_meansBH[CPAD * DN];
__device__ __nv_bfloat16 g_meansBL[CPAD * DN];
__device__ float g_XX[BN];
__device__ float g_YY[CN];
__device__ int   g_lab[BN];
__device__ float g_pb[TSPLIT * BN];
__device__ float g_pp[TSPLIT * BN];
__device__ int   g_pc[TSPLIT * BN];
__device__ float g_ce[BN];
__device__ float g_margin[BN];
__device__ float g_peri[BN];
__device__ float g_valid[BN];

__device__ __forceinline__ uint32_t smem_u32(const void* p) {
    uint32_t a;
    asm("{ .reg .u64 t; cvta.to.shared.u64 t, %1; cvt.u32.u64 %0, t; }" : "=r"(a) : "l"(p));
    return a;
}
__device__ __forceinline__ void bf16_split(float x, __nv_bfloat16& hi, __nv_bfloat16& lo) {
    hi = __float2bfloat16(x);
    lo = __float2bfloat16(x - __bfloat162float(hi));
}

// ---------------- prep -------------------------------------------------------
__global__ void prep_feat_kernel(const float* __restrict__ feat,
                                 const int* __restrict__ labels) {
    int row = blockIdx.x * 8 + threadIdx.y;
    int lane = threadIdx.x;
    float4 v = ((const float4*)(feat + (size_t)row * DN))[lane];
    float ss = v.x * v.x + v.y * v.y + v.z * v.z + v.w * v.w;
    #pragma unroll
    for (int d = 16; d; d >>= 1) ss += __shfl_xor_sync(0xffffffffu, ss, d);
    float inv = 1.0f / fmaxf(sqrtf(ss), 1e-12f);
    float4 o = make_float4(v.x * inv, v.y * inv, v.z * inv, v.w * inv);
    ((float4*)(g_featn + (size_t)row * DN))[lane] = o;

    __nv_bfloat16 hx, lx, hy, ly, hz, lz, hw, lw;
    bf16_split(o.x, hx, lx); bf16_split(o.y, hy, ly);
    bf16_split(o.z, hz, lz); bf16_split(o.w, hw, lw);
    __nv_bfloat162 h0 = __nv_bfloat162(hx, hy), h1 = __nv_bfloat162(hz, hw);
    __nv_bfloat162 l0 = __nv_bfloat162(lx, ly), l1 = __nv_bfloat162(lz, lw);
    ((uint2*)(g_featbH + (size_t)row * DN))[lane] = make_uint2(*(uint32_t*)&h0, *(uint32_t*)&h1);
    ((uint2*)(g_featbL + (size_t)row * DN))[lane] = make_uint2(*(uint32_t*)&l0, *(uint32_t*)&l1);
    if (lane == 0) {
        g_XX[row] = ss * inv * inv;
        g_lab[row] = labels[row];
    }
}

__global__ void prep_means_kernel(const float* __restrict__ means) {
    int row = blockIdx.x * 8 + threadIdx.y;   // 128 blocks * 8 = 1024 (padded)
    int lane = threadIdx.x;
    float4 v = make_float4(0.f, 0.f, 0.f, 0.f);
    if (row < CN) v = ((const float4*)(means + (size_t)row * DN))[lane];
    float ss = v.x * v.x + v.y * v.y + v.z * v.z + v.w * v.w;
    #pragma unroll
    for (int d = 16; d; d >>= 1) ss += __shfl_xor_sync(0xffffffffu, ss, d);
    float inv = 1.0f / fmaxf(sqrtf(ss), 1e-12f);

    __nv_bfloat16 hx, lx, hy, ly, hz, lz, hw, lw;
    bf16_split(v.x, hx, lx); bf16_split(v.y, hy, ly);
    bf16_split(v.z, hz, lz); bf16_split(v.w, hw, lw);
    __nv_bfloat162 h0 = __nv_bfloat162(hx, hy), h1 = __nv_bfloat162(hz, hw);
    __nv_bfloat162 l0 = __nv_bfloat162(lx, ly), l1 = __nv_bfloat162(lz, lw);
    ((uint2*)(g_meansBH + (size_t)row * DN))[lane] = make_uint2(*(uint32_t*)&h0, *(uint32_t*)&h1);
    ((uint2*)(g_meansBL + (size_t)row * DN))[lane] = make_uint2(*(uint32_t*)&l0, *(uint32_t*)&l1);

    if (row < CN) {
        float4 o = make_float4(v.x * inv, v.y * inv, v.z * inv, v.w * inv);
        ((float4*)(g_meansn + (size_t)row * DN))[lane] = o;
        if (lane == 0) g_YY[row] = ss;
    }
}

// copy a 128-row bf16 tile (gmem row-major, DN=128 cols) into padded smem
// each thread: one half-row (128 bytes)
__device__ __forceinline__ void load_tile(char* dst, const __nv_bfloat16* src_base,
                                          int row0, int tid) {
    int r = tid >> 1, h = tid & 1;
    const uint4* src = (const uint4*)(src_base + (size_t)(row0 + r) * DN + h * 64);
    uint4* d = (uint4*)(dst + r * STRIDE + h * 128);
    #pragma unroll
    for (int i = 0; i < 8; i++) d[i] = src[i];
}

// ---------------- nsd GEMM via split-bf16 mma.sync ---------------------------
// XY = Ah*Bh + Ah*Bl + Al*Bh (fp32 accum); out = -0.5*XX + XY - 0.5*YY
__global__ void __launch_bounds__(256) nsd_mma_kernel(float* __restrict__ out) {
    extern __shared__ __align__(16) char sm[];
    char* smX = sm;                       // A_hi, then B_hi
    char* smY = sm + TILE_BYTES;          // A_lo, then B_lo
    float* smYY = (float*)(sm + 2 * TILE_BYTES);

    int tid = threadIdx.x;
    int w = tid >> 5, l = tid & 31;
    int ib = blockIdx.x * 128;
    int cb = blockIdx.y * 128;

    load_tile(smX, g_featbH, ib, tid);
    load_tile(smY, g_featbL, ib, tid);
    __syncthreads();

    uint32_t ah[8][4], al[8][4];
    {
        uint32_t baseH = smem_u32(smX), baseL = smem_u32(smY);
        uint32_t row = 16 * w + (l & 15);
        uint32_t koff = 8 * (l >> 4);
        #pragma unroll
        for (int ks = 0; ks < 8; ks++) {
            uint32_t off = row * STRIDE + (16 * ks + koff) * 2;
            asm volatile("ldmatrix.sync.aligned.m8n8.x4.shared.b16 {%0,%1,%2,%3}, [%4];"
                         : "=r"(ah[ks][0]), "=r"(ah[ks][1]), "=r"(ah[ks][2]), "=r"(ah[ks][3])
                         : "r"(baseH + off));
            asm volatile("ldmatrix.sync.aligned.m8n8.x4.shared.b16 {%0,%1,%2,%3}, [%4];"
                         : "=r"(al[ks][0]), "=r"(al[ks][1]), "=r"(al[ks][2]), "=r"(al[ks][3])
                         : "r"(baseL + off));
        }
    }
    __syncthreads();   // all ldmatrix done before smem reuse

    load_tile(smX, g_meansBH, cb, tid);
    load_tile(smY, g_meansBL, cb, tid);
    if (tid < 128) {
        int c = cb + tid;
        smYY[tid] = (c < CN) ? (-0.5f * g_YY[c]) : 0.f;
    }
    __syncthreads();

    int r0 = 16 * w + (l >> 2), r1 = r0 + 8;
    int i0 = ib + r0, i1 = ib + r1;
    float nx0 = -0.5f * g_XX[i0], nx1 = -0.5f * g_XX[i1];

    uint32_t baseH = smem_u32(smX), baseL = smem_u32(smY);
    uint32_t brow = (l & 7);
    uint32_t bkoff = 8 * (l >> 3);

    #pragma unroll
    for (int nb = 0; nb < 16; nb++) {
        float d0 = 0.f, d1 = 0.f, d2 = 0.f, d3 = 0.f;
        #pragma unroll
        for (int kp = 0; kp < 4; kp++) {
            uint32_t off = (nb * 8 + brow) * STRIDE + (32 * kp + bkoff) * 2;
            uint32_t bh0, bh1, bh2, bh3, bl0, bl1, bl2, bl3;
            asm volatile("ldmatrix.sync.aligned.m8n8.x4.shared.b16 {%0,%1,%2,%3}, [%4];"
                         : "=r"(bh0), "=r"(bh1), "=r"(bh2), "=r"(bh3) : "r"(baseH + off));
            asm volatile("ldmatrix.sync.aligned.m8n8.x4.shared.b16 {%0,%1,%2,%3}, [%4];"
                         : "=r"(bl0), "=r"(bl1), "=r"(bl2), "=r"(bl3) : "r"(baseL + off));
            #define HMMA(A, B0, B1) \
                asm volatile( \
                    "mma.sync.aligned.m16n8k16.row.col.f32.bf16.bf16.f32 " \
                    "{%0,%1,%2,%3}, {%4,%5,%6,%7}, {%8,%9}, {%0,%1,%2,%3};" \
                    : "+f"(d0), "+f"(d1), "+f"(d2), "+f"(d3) \
                    : "r"((A)[0]), "r"((A)[1]), "r"((A)[2]), "r"((A)[3]), "r"(B0), "r"(B1))
            HMMA(ah[2 * kp],     bh0, bh1);
            HMMA(ah[2 * kp + 1], bh2, bh3);
            HMMA(al[2 * kp],     bh0, bh1);
            HMMA(al[2 * kp + 1], bh2, bh3);
            HMMA(ah[2 * kp],     bl0, bl1);
            HMMA(ah[2 * kp + 1], bl2, bl3);
            #undef HMMA
        }
        int colloc = nb * 8 + 2 * (l & 3);
        int col = cb + colloc;
        float y0 = smYY[colloc], y1 = smYY[colloc + 1];
        if (col < CN) {
            out[(size_t)i0 * CN + col] = nx0 + d0 + y0;
            out[(size_t)i1 * CN + col] = nx1 + d2 + y0;
        }
        if (col + 1 < CN) {
            out[(size_t)i0 * CN + col + 1] = nx0 + d1 + y1;
            out[(size_t)i1 * CN + col + 1] = nx1 + d3 + y1;
        }
    }
}

// ---------------- CE + margin: one warp per row ------------------------------
__global__ void __launch_bounds__(256) ce_kernel(const float* __restrict__ nsd) {
    int w = threadIdx.x >> 5, l = threadIdx.x & 31;
    int i = blockIdx.x * 8 + w;
    int lab = g_lab[i];
    const float4* row = (const float4*)(nsd + (size_t)i * CN);

    float4 v[8];
    float m = -1e30f, vlab = -1e30f;
    #pragma unroll
    for (int k = 0; k < 8; k++) {
        int idx = l + 32 * k;
        float4 x = make_float4(-1e30f, -1e30f, -1e30f, -1e30f);
        if (idx < 250) {
            x = row[idx];
            int c0 = idx * 4;
            if (lab == c0)     { x.x *= 1.5f; vlab = x.x; }
            if (lab == c0 + 1) { x.y *= 1.5f; vlab = x.y; }
            if (lab == c0 + 2) { x.z *= 1.5f; vlab = x.z; }
            if (lab == c0 + 3) { x.w *= 1.5f; vlab = x.w; }
            m = fmaxf(m, fmaxf(fmaxf(x.x, x.y), fmaxf(x.z, x.w)));
        }
        v[k] = x;
    }
    #pragma unroll
    for (int d = 16; d; d >>= 1) {
        m = fmaxf(m, __shfl_xor_sync(0xffffffffu, m, d));
        vlab = fmaxf(vlab, __shfl_xor_sync(0xffffffffu, vlab, d));
    }
    float e = 0.f;
    #pragma unroll
    for (int k = 0; k < 8; k++)
        e += __expf(v[k].x - m) + __expf(v[k].y - m)
           + __expf(v[k].z - m) + __expf(v[k].w - m);
    #pragma unroll
    for (int d = 16; d; d >>= 1) e += __shfl_xor_sync(0xffffffffu, e, d);
    if (l == 0) g_ce[i] = -(vlab - m - logf(e));

    float4 f  = ((const float4*)(g_featn  + (size_t)i   * DN))[l];
    float4 mm = ((const float4*)(g_meansn + (size_t)lab * DN))[l];
    float dx = f.x - mm.x, dy = f.y - mm.y, dz = f.z - mm.z, dw = f.w - mm.w;
    float ms = dx * dx + dy * dy + dz * dz + dw * dw;
    #pragma unroll
    for (int d = 16; d; d >>= 1) ms += __shfl_xor_sync(0xffffffffu, ms, d);
    if (l == 0) g_margin[i] = ms;
}

// ---------------- SCL: mma.sync bf16 fused GEMM + row reduction --------------
__global__ void __launch_bounds__(256) scl_mma_kernel() {
    extern __shared__ __align__(16) char sm[];
    char* smA = sm;
    char* smB = sm + TILE_BYTES;
    int* jl = (int*)(sm + 2 * TILE_BYTES);

    int tid = threadIdx.x;
    int w = tid >> 5;
    int l = tid & 31;
    int ib = blockIdx.x * 128;
    int split = blockIdx.y;

    load_tile(smA, g_featbH, ib, tid);
    __syncthreads();

    uint32_t a[8][4];
    {
        uint32_t base = smem_u32(smA);
        uint32_t row = 16 * w + (l & 15);
        uint32_t koff = 8 * (l >> 4);
        #pragma unroll
        for (int ks = 0; ks < 8; ks++) {
            uint32_t addr = base + row * STRIDE + (16 * ks + koff) * 2;
            asm volatile("ldmatrix.sync.aligned.m8n8.x4.shared.b16 {%0,%1,%2,%3}, [%4];"
                         : "=r"(a[ks][0]), "=r"(a[ks][1]), "=r"(a[ks][2]), "=r"(a[ks][3])
                         : "r"(addr));
        }
    }

    int r0 = 16 * w + (l >> 2), r1 = r0 + 8;
    int ig0 = ib + r0, ig1 = ib + r1;
    int lab0 = g_lab[ig0], lab1 = g_lab[ig1];

    const float invT = 1.0f / 0.3f;
    float sB0 = 0.f, sB1 = 0.f, sP0 = 0.f, sP1 = 0.f;
    int sC0 = 0, sC1 = 0;

    uint32_t bbase = smem_u32(smB);
    uint32_t brow = (l & 7);
    uint32_t bkoff = 8 * (l >> 3);

    for (int jt = 0; jt < 64 / TSPLIT; jt++) {
        int jb = (split * (64 / TSPLIT) + jt) * 128;

        __syncthreads();
        load_tile(smB, g_featbH, jb, tid);
        if (tid < 128) jl[tid] = g_lab[jb + tid];
        __syncthreads();

        #pragma unroll
        for (int nb = 0; nb < 16; nb++) {
            float d0 = 0.f, d1 = 0.f, d2 = 0.f, d3 = 0.f;
            #pragma unroll
            for (int kp = 0; kp < 4; kp++) {
                uint32_t b0, b1, b2, b3;
                uint32_t addr = bbase + (nb * 8 + brow) * STRIDE + (32 * kp + bkoff) * 2;
                asm volatile("ldmatrix.sync.aligned.m8n8.x4.shared.b16 {%0,%1,%2,%3}, [%4];"
                             : "=r"(b0), "=r"(b1), "=r"(b2), "=r"(b3) : "r"(addr));
                asm volatile(
                    "mma.sync.aligned.m16n8k16.row.col.f32.bf16.bf16.f32 "
                    "{%0,%1,%2,%3}, {%4,%5,%6,%7}, {%8,%9}, {%0,%1,%2,%3};"
                    : "+f"(d0), "+f"(d1), "+f"(d2), "+f"(d3)
                    : "r"(a[2 * kp][0]), "r"(a[2 * kp][1]), "r"(a[2 * kp][2]), "r"(a[2 * kp][3]),
                      "r"(b0), "r"(b1));
                asm volatile(
                    "mma.sync.aligned.m16n8k16.row.col.f32.bf16.bf16.f32 "
                    "{%0,%1,%2,%3}, {%4,%5,%6,%7}, {%8,%9}, {%0,%1,%2,%3};"
                    : "+f"(d0), "+f"(d1), "+f"(d2), "+f"(d3)
                    : "r"(a[2 * kp + 1][0]), "r"(a[2 * kp + 1][1]), "r"(a[2 * kp + 1][2]), "r"(a[2 * kp + 1][3]),
                      "r"(b2), "r"(b3));
            }
            int col = nb * 8 + 2 * (l & 3);
            int jg0 = jb + col, jg1 = jg0 + 1;
            int jl0 = jl[col], jl1 = jl[col + 1];
            float s0 = d0 * invT, s1 = d1 * invT, s2 = d2 * invT, s3 = d3 * invT;
            if (jg0 != ig0) { sB0 += __expf(s0); if (jl0 == lab0) { sP0 += s0; sC0++; } }
            if (jg1 != ig0) { sB0 += __expf(s1); if (jl1 == lab0) { sP0 += s1; sC0++; } }
            if (jg0 != ig1) { sB1 += __expf(s2); if (jl0 == lab1) { sP1 += s2; sC1++; } }
            if (jg1 != ig1) { sB1 += __expf(s3); if (jl1 == lab1) { sP1 += s3; sC1++; } }
        }
    }

    #pragma unroll
    for (int d = 2; d; d >>= 1) {
        sB0 += __shfl_down_sync(0xffffffffu, sB0, d, 4);
        sB1 += __shfl_down_sync(0xffffffffu, sB1, d, 4);
        sP0 += __shfl_down_sync(0xffffffffu, sP0, d, 4);
        sP1 += __shfl_down_sync(0xffffffffu, sP1, d, 4);
        sC0 += __shfl_down_sync(0xffffffffu, sC0, d, 4);
        sC1 += __shfl_down_sync(0xffffffffu, sC1, d, 4);
    }
    if ((l & 3) == 0) {
        g_pb[split * BN + ig0] = sB0;
        g_pp[split * BN + ig0] = sP0;
        g_pc[split * BN + ig0] = sC0;
        g_pb[split * BN + ig1] = sB1;
        g_pp[split * BN + ig1] = sP1;
        g_pc[split * BN + ig1] = sC1;
    }
}

// ---------------- combine + final --------------------------------------------
__global__ void combine_kernel() {
    int i = blockIdx.x * 256 + threadIdx.x;
    float b = 0.f, p = 0.f;
    int c = 0;
    #pragma unroll
    for (int s = 0; s < TSPLIT; s++) {
        b += g_pb[s * BN + i];
        p += g_pp[s * BN + i];
        c += g_pc[s * BN + i];
    }
    bool valid = (c > 0);
    g_peri[i]  = valid ? (p / (float)c - logf(b)) : 0.f;
    g_valid[i] = valid ? 1.f : 0.f;
}

__global__ void final_kernel(float* __restrict__ out, long long scalar_idx) {
    int t = threadIdx.x;
    float sp = 0.f, sv = 0.f, sc = 0.f, smg = 0.f;
    for (int i = t; i < BN; i += 256) {
        sp += g_peri[i];
        sv += g_valid[i];
        sc += g_ce[i];
        smg += g_margin[i];
    }
    __shared__ float r0[256], r1[256], r2[256], r3[256];
    r0[t] = sp; r1[t] = sv; r2[t] = sc; r3[t] = smg;
    __syncthreads();
    for (int d = 128; d; d >>= 1) {
        if (t < d) { r0[t] += r0[t+d]; r1[t] += r1[t+d]; r2[t] += r2[t+d]; r3[t] += r3[t+d]; }
        __syncthreads();
    }
    if (t == 0) {
        float scl = -r0[0] / fmaxf(r1[0], 1.f);
        float ce  = r2[0] / (float)BN;
        float lm  = r3[0] / (2.f * (float)BN);
        out[scalar_idx] = 0.9f * ce + 0.1f * scl + 0.5f * lm;
    }
}

// ---------------- launch ------------------------------------------------------
extern "C" void kernel_launch(void* const* d_in, const int* in_sizes, int n_in,
                              void* d_out, int out_size) {
    const float* feat   = (const float*)d_in[0];
    const int*   labels = (const int*)d_in[1];
    const float* means  = (const float*)d_in[2];
    float* out = (float*)d_out;

    static cudaStream_t sB = nullptr;
    static cudaEvent_t  eF = nullptr, eJ = nullptr;
    static int initTried = 0;
    if (!initTried) {
        initTried = 1;
        if (cudaStreamCreateWithFlags(&sB, cudaStreamNonBlocking) != cudaSuccess) sB = nullptr;
        if (sB) {
            if (cudaEventCreateWithFlags(&eF, cudaEventDisableTiming) != cudaSuccess) { eF = nullptr; }
            if (cudaEventCreateWithFlags(&eJ, cudaEventDisableTiming) != cudaSuccess) { eJ = nullptr; }
            if (!eF || !eJ) sB = nullptr;
        }
        cudaFuncSetAttribute(nsd_mma_kernel, cudaFuncAttributeMaxDynamicSharedMemorySize, SMEM_TOT);
        cudaFuncSetAttribute(scl_mma_kernel, cudaFuncAttributeMaxDynamicSharedMemorySize, SMEM_TOT);
    }
    bool fork = (sB != nullptr);

    prep_feat_kernel<<<BN / 8, dim3(32, 8)>>>(feat, labels);

    if (fork) {
        cudaEventRecord(eF, 0);
        cudaStreamWaitEvent(sB, eF, 0);
        scl_mma_kernel<<<dim3(BN / 128, TSPLIT), 256, SMEM_TOT, sB>>>();
        cudaEventRecord(eJ, sB);
    }

    prep_means_kernel<<<CPAD / 8, dim3(32, 8)>>>(means);
    nsd_mma_kernel<<<dim3(BN / 128, CPAD / 128), 256, SMEM_TOT>>>(out);
    ce_kernel<<<BN / 8, 256>>>(out);

    if (fork) {
        cudaStreamWaitEvent(0, eJ, 0);
    } else {
        scl_mma_kernel<<<dim3(BN / 128, TSPLIT), 256, SMEM_TOT>>>();
    }

    combine_kernel<<<BN / 256, 256>>>();
    final_kernel<<<1, 256>>>(out, (long long)out_size - 1);
}

// round 10
// speedup vs baseline: 3.2480x; 1.0112x over previous
#include <cuda_runtime.h>
#include <cuda_bf16.h>
#include <math.h>
#include <cstdint>

#define BN 8192
#define CN 1000
#define CPAD 1024
#define DN 128
#define TSPLIT 16
#define STRIDE 272                 // bytes per tile row: 256 data + 16 pad (conflict-free ldmatrix)
#define TILE_BYTES (128 * STRIDE)  // 34816
#define SMEM_NSD (2 * TILE_BYTES + 512)
#define SMEM_SCL (TILE_BYTES + 512)

// ---------------- scratch ---------------------------------------------------
__device__ float g_featn[BN * DN];
__device__ __nv_bfloat16 g_featbH[BN * DN];
__device__ __nv_bfloat16 g_featbL[BN * DN];
__device__ float g_meansn[CN * DN];
__device__ __nv_bfloat16 g_meansBH[CPAD * DN];
__device__ __nv_bfloat16 g_meansBL[CPAD * DN];
__device__ float g_XX[BN];
__device__ float g_YY[CN];
__device__ int   g_lab[BN];
__device__ float g_pb[TSPLIT * BN];
__device__ float g_pp[TSPLIT * BN];
__device__ int   g_pc[TSPLIT * BN];
__device__ float g_ce[BN];
__device__ float g_margin[BN];
__device__ float g_peri[BN];
__device__ float g_valid[BN];

__device__ __forceinline__ uint32_t smem_u32(const void* p) {
    uint32_t a;
    asm("{ .reg .u64 t; cvta.to.shared.u64 t, %1; cvt.u32.u64 %0, t; }" : "=r"(a) : "l"(p));
    return a;
}
__device__ __forceinline__ void bf16_split(float x, __nv_bfloat16& hi, __nv_bfloat16& lo) {
    hi = __float2bfloat16(x);
    lo = __float2bfloat16(x - __bfloat162float(hi));
}

// non-volatile MMA: pure register op, lets ptxas interleave independent chains
#define HMMA4(ACC, A, B0, B1) \
    asm("mma.sync.aligned.m16n8k16.row.col.f32.bf16.bf16.f32 " \
        "{%0,%1,%2,%3}, {%4,%5,%6,%7}, {%8,%9}, {%0,%1,%2,%3};" \
        : "+f"((ACC)[0]), "+f"((ACC)[1]), "+f"((ACC)[2]), "+f"((ACC)[3]) \
        : "r"((A)[0]), "r"((A)[1]), "r"((A)[2]), "r"((A)[3]), "r"(B0), "r"(B1))

#define LDSM4(R, ADDR) \
    asm volatile("ldmatrix.sync.aligned.m8n8.x4.shared.b16 {%0,%1,%2,%3}, [%4];" \
                 : "=r"((R)[0]), "=r"((R)[1]), "=r"((R)[2]), "=r"((R)[3]) : "r"(ADDR))

// ---------------- prep -------------------------------------------------------
__global__ void prep_feat_kernel(const float* __restrict__ feat,
                                 const int* __restrict__ labels) {
    int row = blockIdx.x * 8 + threadIdx.y;
    int lane = threadIdx.x;
    float4 v = ((const float4*)(feat + (size_t)row * DN))[lane];
    float ss = v.x * v.x + v.y * v.y + v.z * v.z + v.w * v.w;
    #pragma unroll
    for (int d = 16; d; d >>= 1) ss += __shfl_xor_sync(0xffffffffu, ss, d);
    float inv = 1.0f / fmaxf(sqrtf(ss), 1e-12f);
    float4 o = make_float4(v.x * inv, v.y * inv, v.z * inv, v.w * inv);
    ((float4*)(g_featn + (size_t)row * DN))[lane] = o;

    __nv_bfloat16 hx, lx, hy, ly, hz, lz, hw, lw;
    bf16_split(o.x, hx, lx); bf16_split(o.y, hy, ly);
    bf16_split(o.z, hz, lz); bf16_split(o.w, hw, lw);
    __nv_bfloat162 h0 = __nv_bfloat162(hx, hy), h1 = __nv_bfloat162(hz, hw);
    __nv_bfloat162 l0 = __nv_bfloat162(lx, ly), l1 = __nv_bfloat162(lz, lw);
    ((uint2*)(g_featbH + (size_t)row * DN))[lane] = make_uint2(*(uint32_t*)&h0, *(uint32_t*)&h1);
    ((uint2*)(g_featbL + (size_t)row * DN))[lane] = make_uint2(*(uint32_t*)&l0, *(uint32_t*)&l1);
    if (lane == 0) {
        g_XX[row] = ss * inv * inv;
        g_lab[row] = labels[row];
    }
}

__global__ void prep_means_kernel(const float* __restrict__ means) {
    int row = blockIdx.x * 8 + threadIdx.y;   // 128 blocks * 8 = 1024 (padded)
    int lane = threadIdx.x;
    float4 v = make_float4(0.f, 0.f, 0.f, 0.f);
    if (row < CN) v = ((const float4*)(means + (size_t)row * DN))[lane];
    float ss = v.x * v.x + v.y * v.y + v.z * v.z + v.w * v.w;
    #pragma unroll
    for (int d = 16; d; d >>= 1) ss += __shfl_xor_sync(0xffffffffu, ss, d);
    float inv = 1.0f / fmaxf(sqrtf(ss), 1e-12f);

    __nv_bfloat16 hx, lx, hy, ly, hz, lz, hw, lw;
    bf16_split(v.x, hx, lx); bf16_split(v.y, hy, ly);
    bf16_split(v.z, hz, lz); bf16_split(v.w, hw, lw);
    __nv_bfloat162 h0 = __nv_bfloat162(hx, hy), h1 = __nv_bfloat162(hz, hw);
    __nv_bfloat162 l0 = __nv_bfloat162(lx, ly), l1 = __nv_bfloat162(lz, lw);
    ((uint2*)(g_meansBH + (size_t)row * DN))[lane] = make_uint2(*(uint32_t*)&h0, *(uint32_t*)&h1);
    ((uint2*)(g_meansBL + (size_t)row * DN))[lane] = make_uint2(*(uint32_t*)&l0, *(uint32_t*)&l1);

    if (row < CN) {
        float4 o = make_float4(v.x * inv, v.y * inv, v.z * inv, v.w * inv);
        ((float4*)(g_meansn + (size_t)row * DN))[lane] = o;
        if (lane == 0) g_YY[row] = ss;
    }
}

// copy a 128-row bf16 tile into padded smem; each thread: one half-row (128 B)
__device__ __forceinline__ void load_tile(char* dst, const __nv_bfloat16* src_base,
                                          int row0, int tid) {
    int r = tid >> 1, h = tid & 1;
    const uint4* src = (const uint4*)(src_base + (size_t)(row0 + r) * DN + h * 64);
    uint4* d = (uint4*)(dst + r * STRIDE + h * 128);
    #pragma unroll
    for (int i = 0; i < 8; i++) d[i] = src[i];
}

// extract a warp's 16-row A fragments (8 k-steps)
__device__ __forceinline__ void load_a_frags(uint32_t base, int w, int l, uint32_t a[8][4]) {
    uint32_t row = 16 * w + (l & 15);
    uint32_t koff = 8 * (l >> 4);
    #pragma unroll
    for (int ks = 0; ks < 8; ks++) {
        uint32_t addr = base + row * STRIDE + (16 * ks + koff) * 2;
        LDSM4(a[ks], addr);
    }
}

// ---------------- nsd GEMM via split-bf16 mma.sync ---------------------------
// XY = Ah*Bh + Ah*Bl + Al*Bh (fp32 accum, 3 independent chains); out = -0.5*XX + XY - 0.5*YY
__global__ void __launch_bounds__(256) nsd_mma_kernel(float* __restrict__ out) {
    extern __shared__ __align__(16) char sm[];
    char* smX = sm;                       // A_hi, then B_hi
    char* smY = sm + TILE_BYTES;          // A_lo, then B_lo
    float* smYY = (float*)(sm + 2 * TILE_BYTES);

    int tid = threadIdx.x;
    int w = tid >> 5, l = tid & 31;
    int ib = blockIdx.x * 128;
    int cb = blockIdx.y * 128;

    load_tile(smX, g_featbH, ib, tid);
    load_tile(smY, g_featbL, ib, tid);
    __syncthreads();

    uint32_t ah[8][4], al[8][4];
    load_a_frags(smem_u32(smX), w, l, ah);
    load_a_frags(smem_u32(smY), w, l, al);
    __syncthreads();   // all ldmatrix done before smem reuse

    load_tile(smX, g_meansBH, cb, tid);
    load_tile(smY, g_meansBL, cb, tid);
    if (tid < 128) {
        int c = cb + tid;
        smYY[tid] = (c < CN) ? (-0.5f * g_YY[c]) : 0.f;
    }
    __syncthreads();

    int r0 = 16 * w + (l >> 2), r1 = r0 + 8;
    int i0 = ib + r0, i1 = ib + r1;
    float nx0 = -0.5f * g_XX[i0], nx1 = -0.5f * g_XX[i1];

    uint32_t baseH = smem_u32(smX), baseL = smem_u32(smY);
    uint32_t brow = (l & 7);
    uint32_t bkoff = 8 * (l >> 3);

    #pragma unroll
    for (int nb = 0; nb < 16; nb++) {
        float hh[4] = {0.f, 0.f, 0.f, 0.f};
        float lh[4] = {0.f, 0.f, 0.f, 0.f};
        float hl[4] = {0.f, 0.f, 0.f, 0.f};
        #pragma unroll
        for (int kp = 0; kp < 4; kp++) {
            uint32_t off = (nb * 8 + brow) * STRIDE + (32 * kp + bkoff) * 2;
            uint32_t bh[4], bl[4];
            LDSM4(bh, baseH + off);
            LDSM4(bl, baseL + off);
            HMMA4(hh, ah[2 * kp],     bh[0], bh[1]);
            HMMA4(lh, al[2 * kp],     bh[0], bh[1]);
            HMMA4(hl, ah[2 * kp],     bl[0], bl[1]);
            HMMA4(hh, ah[2 * kp + 1], bh[2], bh[3]);
            HMMA4(lh, al[2 * kp + 1], bh[2], bh[3]);
            HMMA4(hl, ah[2 * kp + 1], bl[2], bl[3]);
        }
        int colloc = nb * 8 + 2 * (l & 3);
        int col = cb + colloc;
        float y0 = smYY[colloc], y1 = smYY[colloc + 1];
        if (col < CN) {
            out[(size_t)i0 * CN + col] = nx0 + (hh[0] + lh[0] + hl[0]) + y0;
            out[(size_t)i1 * CN + col] = nx1 + (hh[2] + lh[2] + hl[2]) + y0;
        }
        if (col + 1 < CN) {
            out[(size_t)i0 * CN + col + 1] = nx0 + (hh[1] + lh[1] + hl[1]) + y1;
            out[(size_t)i1 * CN + col + 1] = nx1 + (hh[3] + lh[3] + hl[3]) + y1;
        }
    }
}

// ---------------- CE + margin: one warp per row ------------------------------
__global__ void __launch_bounds__(256) ce_kernel(const float* __restrict__ nsd) {
    int w = threadIdx.x >> 5, l = threadIdx.x & 31;
    int i = blockIdx.x * 8 + w;
    int lab = g_lab[i];
    const float4* row = (const float4*)(nsd + (size_t)i * CN);

    float4 v[8];
    float m = -1e30f, vlab = -1e30f;
    #pragma unroll
    for (int k = 0; k < 8; k++) {
        int idx = l + 32 * k;
        float4 x = make_float4(-1e30f, -1e30f, -1e30f, -1e30f);
        if (idx < 250) {
            x = row[idx];
            int c0 = idx * 4;
            if (lab == c0)     { x.x *= 1.5f; vlab = x.x; }
            if (lab == c0 + 1) { x.y *= 1.5f; vlab = x.y; }
            if (lab == c0 + 2) { x.z *= 1.5f; vlab = x.z; }
            if (lab == c0 + 3) { x.w *= 1.5f; vlab = x.w; }
            m = fmaxf(m, fmaxf(fmaxf(x.x, x.y), fmaxf(x.z, x.w)));
        }
        v[k] = x;
    }
    #pragma unroll
    for (int d = 16; d; d >>= 1) {
        m = fmaxf(m, __shfl_xor_sync(0xffffffffu, m, d));
        vlab = fmaxf(vlab, __shfl_xor_sync(0xffffffffu, vlab, d));
    }
    float e = 0.f;
    #pragma unroll
    for (int k = 0; k < 8; k++)
        e += __expf(v[k].x - m) + __expf(v[k].y - m)
           + __expf(v[k].z - m) + __expf(v[k].w - m);
    #pragma unroll
    for (int d = 16; d; d >>= 1) e += __shfl_xor_sync(0xffffffffu, e, d);
    if (l == 0) g_ce[i] = -(vlab - m - logf(e));

    float4 f  = ((const float4*)(g_featn  + (size_t)i   * DN))[l];
    float4 mm = ((const float4*)(g_meansn + (size_t)lab * DN))[l];
    float dx = f.x - mm.x, dy = f.y - mm.y, dz = f.z - mm.z, dw = f.w - mm.w;
    float ms = dx * dx + dy * dy + dz * dz + dw * dw;
    #pragma unroll
    for (int d = 16; d; d >>= 1) ms += __shfl_xor_sync(0xffffffffu, ms, d);
    if (l == 0) g_margin[i] = ms;
}

// ---------------- SCL: mma.sync bf16 fused GEMM + row reduction --------------
// single smem tile buffer (A staged first, then reused for B tiles)
__global__ void __launch_bounds__(256) scl_mma_kernel() {
    extern __shared__ __align__(16) char sm[];
    char* smT = sm;
    int* jl = (int*)(sm + TILE_BYTES);

    int tid = threadIdx.x;
    int w = tid >> 5;
    int l = tid & 31;
    int ib = blockIdx.x * 128;
    int split = blockIdx.y;

    load_tile(smT, g_featbH, ib, tid);
    __syncthreads();

    uint32_t a[8][4];
    load_a_frags(smem_u32(smT), w, l, a);
    __syncthreads();   // A frags extracted; buffer free for B

    int r0 = 16 * w + (l >> 2), r1 = r0 + 8;
    int ig0 = ib + r0, ig1 = ib + r1;
    int lab0 = g_lab[ig0], lab1 = g_lab[ig1];

    const float invT = 1.0f / 0.3f;
    float sB0 = 0.f, sB1 = 0.f, sP0 = 0.f, sP1 = 0.f;
    int sC0 = 0, sC1 = 0;

    uint32_t bbase = smem_u32(smT);
    uint32_t brow = (l & 7);
    uint32_t bkoff = 8 * (l >> 3);

    for (int jt = 0; jt < 64 / TSPLIT; jt++) {
        int jb = (split * (64 / TSPLIT) + jt) * 128;

        load_tile(smT, g_featbH, jb, tid);
        if (tid < 128) jl[tid] = g_lab[jb + tid];
        __syncthreads();

        #pragma unroll
        for (int nbp = 0; nbp < 8; nbp++) {
            int nb0 = 2 * nbp, nb1 = nb0 + 1;
            // 4 independent accumulator chains (2 nb x even/odd kp)
            float e0[4] = {0.f, 0.f, 0.f, 0.f}, o0[4] = {0.f, 0.f, 0.f, 0.f};
            float e1[4] = {0.f, 0.f, 0.f, 0.f}, o1[4] = {0.f, 0.f, 0.f, 0.f};
            #pragma unroll
            for (int kp = 0; kp < 4; kp++) {
                uint32_t b0[4], b1[4];
                LDSM4(b0, bbase + (nb0 * 8 + brow) * STRIDE + (32 * kp + bkoff) * 2);
                LDSM4(b1, bbase + (nb1 * 8 + brow) * STRIDE + (32 * kp + bkoff) * 2);
                HMMA4(e0, a[2 * kp],     b0[0], b0[1]);
                HMMA4(e1, a[2 * kp],     b1[0], b1[1]);
                HMMA4(o0, a[2 * kp + 1], b0[2], b0[3]);
                HMMA4(o1, a[2 * kp + 1], b1[2], b1[3]);
            }
            #pragma unroll
            for (int half = 0; half < 2; half++) {
                const float* ee = half ? e1 : e0;
                const float* oo = half ? o1 : o0;
                int nb = half ? nb1 : nb0;
                int col = nb * 8 + 2 * (l & 3);
                int jg0 = jb + col, jg1 = jg0 + 1;
                int jl0 = jl[col], jl1 = jl[col + 1];
                float s0 = (ee[0] + oo[0]) * invT, s1 = (ee[1] + oo[1]) * invT;
                float s2 = (ee[2] + oo[2]) * invT, s3 = (ee[3] + oo[3]) * invT;
                if (jg0 != ig0) { sB0 += __expf(s0); if (jl0 == lab0) { sP0 += s0; sC0++; } }
                if (jg1 != ig0) { sB0 += __expf(s1); if (jl1 == lab0) { sP0 += s1; sC0++; } }
                if (jg0 != ig1) { sB1 += __expf(s2); if (jl0 == lab1) { sP1 += s2; sC1++; } }
                if (jg1 != ig1) { sB1 += __expf(s3); if (jl1 == lab1) { sP1 += s3; sC1++; } }
            }
        }
        __syncthreads();   // all ldmatrix of this tile done before next overwrite
    }

    #pragma unroll
    for (int d = 2; d; d >>= 1) {
        sB0 += __shfl_down_sync(0xffffffffu, sB0, d, 4);
        sB1 += __shfl_down_sync(0xffffffffu, sB1, d, 4);
        sP0 += __shfl_down_sync(0xffffffffu, sP0, d, 4);
        sP1 += __shfl_down_sync(0xffffffffu, sP1, d, 4);
        sC0 += __shfl_down_sync(0xffffffffu, sC0, d, 4);
        sC1 += __shfl_down_sync(0xffffffffu, sC1, d, 4);
    }
    if ((l & 3) == 0) {
        g_pb[split * BN + ig0] = sB0;
        g_pp[split * BN + ig0] = sP0;
        g_pc[split * BN + ig0] = sC0;
        g_pb[split * BN + ig1] = sB1;
        g_pp[split * BN + ig1] = sP1;
        g_pc[split * BN + ig1] = sC1;
    }
}

// ---------------- combine + final --------------------------------------------
__global__ void combine_kernel() {
    int i = blockIdx.x * 256 + threadIdx.x;
    float b = 0.f, p = 0.f;
    int c = 0;
    #pragma unroll
    for (int s = 0; s < TSPLIT; s++) {
        b += g_pb[s * BN + i];
        p += g_pp[s * BN + i];
        c += g_pc[s * BN + i];
    }
    bool valid = (c > 0);
    g_peri[i]  = valid ? (p / (float)c - logf(b)) : 0.f;
    g_valid[i] = valid ? 1.f : 0.f;
}

__global__ void final_kernel(float* __restrict__ out, long long scalar_idx) {
    int t = threadIdx.x;
    float sp = 0.f, sv = 0.f, sc = 0.f, smg = 0.f;
    for (int i = t; i < BN; i += 256) {
        sp += g_peri[i];
        sv += g_valid[i];
        sc += g_ce[i];
        smg += g_margin[i];
    }
    __shared__ float r0[256], r1[256], r2[256], r3[256];
    r0[t] = sp; r1[t] = sv; r2[t] = sc; r3[t] = smg;
    __syncthreads();
    for (int d = 128; d; d >>= 1) {
        if (t < d) { r0[t] += r0[t+d]; r1[t] += r1[t+d]; r2[t] += r2[t+d]; r3[t] += r3[t+d]; }
        __syncthreads();
    }
    if (t == 0) {
        float scl = -r0[0] / fmaxf(r1[0], 1.f);
        float ce  = r2[0] / (float)BN;
        float lm  = r3[0] / (2.f * (float)BN);
        out[scalar_idx] = 0.9f * ce + 0.1f * scl + 0.5f * lm;
    }
}

// ---------------- launch ------------------------------------------------------
extern "C" void kernel_launch(void* const* d_in, const int* in_sizes, int n_in,
                              void* d_out, int out_size) {
    const float* feat   = (const float*)d_in[0];
    const int*   labels = (const int*)d_in[1];
    const float* means  = (const float*)d_in[2];
    float* out = (float*)d_out;

    static cudaStream_t sB = nullptr;
    static cudaEvent_t  eF = nullptr, eJ = nullptr;
    static int initTried = 0;
    if (!initTried) {
        initTried = 1;
        if (cudaStreamCreateWithFlags(&sB, cudaStreamNonBlocking) != cudaSuccess) sB = nullptr;
        if (sB) {
            if (cudaEventCreateWithFlags(&eF, cudaEventDisableTiming) != cudaSuccess) { eF = nullptr; }
            if (cudaEventCreateWithFlags(&eJ, cudaEventDisableTiming) != cudaSuccess) { eJ = nullptr; }
            if (!eF || !eJ) sB = nullptr;
        }
        cudaFuncSetAttribute(nsd_mma_kernel, cudaFuncAttributeMaxDynamicSharedMemorySize, SMEM_NSD);
        cudaFuncSetAttribute(scl_mma_kernel, cudaFuncAttributeMaxDynamicSharedMemorySize, SMEM_SCL);
    }
    bool fork = (sB != nullptr);

    prep_feat_kernel<<<BN / 8, dim3(32, 8)>>>(feat, labels);

    if (fork) {
        cudaEventRecord(eF, 0);
        cudaStreamWaitEvent(sB, eF, 0);
        scl_mma_kernel<<<dim3(BN / 128, TSPLIT), 256, SMEM_SCL, sB>>>();
        cudaEventRecord(eJ, sB);
    }

    prep_means_kernel<<<CPAD / 8, dim3(32, 8)>>>(means);
    nsd_mma_kernel<<<dim3(BN / 128, CPAD / 128), 256, SMEM_NSD>>>(out);
    ce_kernel<<<BN / 8, 256>>>(out);

    if (fork) {
        cudaStreamWaitEvent(0, eJ, 0);
    } else {
        scl_mma_kernel<<<dim3(BN / 128, TSPLIT), 256, SMEM_SCL>>>();
    }

    combine_kernel<<<BN / 256, 256>>>();
    final_kernel<<<1, 256>>>(out, (long long)out_size - 1);
}

// round 11
// speedup vs baseline: 3.7862x; 1.1657x over previous
#include <cuda_runtime.h>
#include <cuda_bf16.h>
#include <math.h>
#include <cstdint>

#define BN 8192
#define CN 1000
#define CPAD 1024
#define DN 128
#define TSPLIT 8
#define STRIDE 272                 // bytes per tile row: 256 data + 16 pad (conflict-free ldmatrix)
#define TILE_BYTES (128 * STRIDE)  // 34816
#define SMEM_NSD (2 * TILE_BYTES + 512)
#define SMEM_SCL (TILE_BYTES + 512)

// ---------------- scratch ---------------------------------------------------
__device__ float g_featn[BN * DN];
__device__ __nv_bfloat16 g_featbH[BN * DN];
__device__ __nv_bfloat16 g_featbL[BN * DN];
__device__ float g_meansn[CN * DN];
__device__ __nv_bfloat16 g_meansBH[CPAD * DN];
__device__ __nv_bfloat16 g_meansBL[CPAD * DN];
__device__ float g_XX[BN];
__device__ float g_YY[CN];
__device__ int   g_lab[BN];
__device__ float g_pb[TSPLIT * BN];
__device__ float g_pp[TSPLIT * BN];
__device__ int   g_pc[TSPLIT * BN];
__device__ float g_ce[BN];
__device__ float g_margin[BN];
__device__ float g_peri[BN];
__device__ float g_valid[BN];

__device__ __forceinline__ uint32_t smem_u32(const void* p) {
    uint32_t a;
    asm("{ .reg .u64 t; cvta.to.shared.u64 t, %1; cvt.u32.u64 %0, t; }" : "=r"(a) : "l"(p));
    return a;
}
__device__ __forceinline__ void bf16_split(float x, __nv_bfloat16& hi, __nv_bfloat16& lo) {
    hi = __float2bfloat16(x);
    lo = __float2bfloat16(x - __bfloat162float(hi));
}

// non-volatile MMA: pure register op, lets ptxas interleave independent chains
#define HMMA4(ACC, A, B0, B1) \
    asm("mma.sync.aligned.m16n8k16.row.col.f32.bf16.bf16.f32 " \
        "{%0,%1,%2,%3}, {%4,%5,%6,%7}, {%8,%9}, {%0,%1,%2,%3};" \
        : "+f"((ACC)[0]), "+f"((ACC)[1]), "+f"((ACC)[2]), "+f"((ACC)[3]) \
        : "r"((A)[0]), "r"((A)[1]), "r"((A)[2]), "r"((A)[3]), "r"(B0), "r"(B1))

#define LDSM4(R, ADDR) \
    asm volatile("ldmatrix.sync.aligned.m8n8.x4.shared.b16 {%0,%1,%2,%3}, [%4];" \
                 : "=r"((R)[0]), "=r"((R)[1]), "=r"((R)[2]), "=r"((R)[3]) : "r"(ADDR))

// ---------------- prep -------------------------------------------------------
__global__ void prep_feat_kernel(const float* __restrict__ feat,
                                 const int* __restrict__ labels) {
    int row = blockIdx.x * 8 + threadIdx.y;
    int lane = threadIdx.x;
    float4 v = ((const float4*)(feat + (size_t)row * DN))[lane];
    float ss = v.x * v.x + v.y * v.y + v.z * v.z + v.w * v.w;
    #pragma unroll
    for (int d = 16; d; d >>= 1) ss += __shfl_xor_sync(0xffffffffu, ss, d);
    float inv = 1.0f / fmaxf(sqrtf(ss), 1e-12f);
    float4 o = make_float4(v.x * inv, v.y * inv, v.z * inv, v.w * inv);
    ((float4*)(g_featn + (size_t)row * DN))[lane] = o;

    __nv_bfloat16 hx, lx, hy, ly, hz, lz, hw, lw;
    bf16_split(o.x, hx, lx); bf16_split(o.y, hy, ly);
    bf16_split(o.z, hz, lz); bf16_split(o.w, hw, lw);
    __nv_bfloat162 h0 = __nv_bfloat162(hx, hy), h1 = __nv_bfloat162(hz, hw);
    __nv_bfloat162 l0 = __nv_bfloat162(lx, ly), l1 = __nv_bfloat162(lz, lw);
    ((uint2*)(g_featbH + (size_t)row * DN))[lane] = make_uint2(*(uint32_t*)&h0, *(uint32_t*)&h1);
    ((uint2*)(g_featbL + (size_t)row * DN))[lane] = make_uint2(*(uint32_t*)&l0, *(uint32_t*)&l1);
    if (lane == 0) {
        g_XX[row] = ss * inv * inv;
        g_lab[row] = labels[row];
    }
}

__global__ void prep_means_kernel(const float* __restrict__ means) {
    int row = blockIdx.x * 8 + threadIdx.y;   // 128 blocks * 8 = 1024 (padded)
    int lane = threadIdx.x;
    float4 v = make_float4(0.f, 0.f, 0.f, 0.f);
    if (row < CN) v = ((const float4*)(means + (size_t)row * DN))[lane];
    float ss = v.x * v.x + v.y * v.y + v.z * v.z + v.w * v.w;
    #pragma unroll
    for (int d = 16; d; d >>= 1) ss += __shfl_xor_sync(0xffffffffu, ss, d);
    float inv = 1.0f / fmaxf(sqrtf(ss), 1e-12f);

    __nv_bfloat16 hx, lx, hy, ly, hz, lz, hw, lw;
    bf16_split(v.x, hx, lx); bf16_split(v.y, hy, ly);
    bf16_split(v.z, hz, lz); bf16_split(v.w, hw, lw);
    __nv_bfloat162 h0 = __nv_bfloat162(hx, hy), h1 = __nv_bfloat162(hz, hw);
    __nv_bfloat162 l0 = __nv_bfloat162(lx, ly), l1 = __nv_bfloat162(lz, lw);
    ((uint2*)(g_meansBH + (size_t)row * DN))[lane] = make_uint2(*(uint32_t*)&h0, *(uint32_t*)&h1);
    ((uint2*)(g_meansBL + (size_t)row * DN))[lane] = make_uint2(*(uint32_t*)&l0, *(uint32_t*)&l1);

    if (row < CN) {
        float4 o = make_float4(v.x * inv, v.y * inv, v.z * inv, v.w * inv);
        ((float4*)(g_meansn + (size_t)row * DN))[lane] = o;
        if (lane == 0) g_YY[row] = ss;
    }
}

// copy a 128-row bf16 tile into padded smem; each thread: one half-row (128 B)
__device__ __forceinline__ void load_tile(char* dst, const __nv_bfloat16* src_base,
                                          int row0, int tid) {
    int r = tid >> 1, h = tid & 1;
    const uint4* src = (const uint4*)(src_base + (size_t)(row0 + r) * DN + h * 64);
    uint4* d = (uint4*)(dst + r * STRIDE + h * 128);
    #pragma unroll
    for (int i = 0; i < 8; i++) d[i] = src[i];
}

// extract a warp's 16-row A fragments (8 k-steps) starting at tile row `row0`
__device__ __forceinline__ void load_a_frags16(uint32_t base, int row0, int l, uint32_t a[8][4]) {
    uint32_t row = row0 + (l & 15);
    uint32_t koff = 8 * (l >> 4);
    #pragma unroll
    for (int ks = 0; ks < 8; ks++) {
        uint32_t addr = base + row * STRIDE + (16 * ks + koff) * 2;
        LDSM4(a[ks], addr);
    }
}

// ---------------- nsd GEMM via split-bf16 mma.sync ---------------------------
// XY = Ah*Bh + Ah*Bl + Al*Bh (fp32 accum, 3 independent chains); out = -0.5*XX + XY - 0.5*YY
__global__ void __launch_bounds__(256) nsd_mma_kernel(float* __restrict__ out) {
    extern __shared__ __align__(16) char sm[];
    char* smX = sm;                       // A_hi, then B_hi
    char* smY = sm + TILE_BYTES;          // A_lo, then B_lo
    float* smYY = (float*)(sm + 2 * TILE_BYTES);

    int tid = threadIdx.x;
    int w = tid >> 5, l = tid & 31;
    int ib = blockIdx.x * 128;
    int cb = blockIdx.y * 128;

    load_tile(smX, g_featbH, ib, tid);
    load_tile(smY, g_featbL, ib, tid);
    __syncthreads();

    uint32_t ah[8][4], al[8][4];
    load_a_frags16(smem_u32(smX), 16 * w, l, ah);
    load_a_frags16(smem_u32(smY), 16 * w, l, al);
    __syncthreads();   // all ldmatrix done before smem reuse

    load_tile(smX, g_meansBH, cb, tid);
    load_tile(smY, g_meansBL, cb, tid);
    if (tid < 128) {
        int c = cb + tid;
        smYY[tid] = (c < CN) ? (-0.5f * g_YY[c]) : 0.f;
    }
    __syncthreads();

    int r0 = 16 * w + (l >> 2), r1 = r0 + 8;
    int i0 = ib + r0, i1 = ib + r1;
    float nx0 = -0.5f * g_XX[i0], nx1 = -0.5f * g_XX[i1];

    uint32_t baseH = smem_u32(smX), baseL = smem_u32(smY);
    uint32_t brow = (l & 7);
    uint32_t bkoff = 8 * (l >> 3);

    #pragma unroll
    for (int nb = 0; nb < 16; nb++) {
        float hh[4] = {0.f, 0.f, 0.f, 0.f};
        float lh[4] = {0.f, 0.f, 0.f, 0.f};
        float hl[4] = {0.f, 0.f, 0.f, 0.f};
        #pragma unroll
        for (int kp = 0; kp < 4; kp++) {
            uint32_t off = (nb * 8 + brow) * STRIDE + (32 * kp + bkoff) * 2;
            uint32_t bh[4], bl[4];
            LDSM4(bh, baseH + off);
            LDSM4(bl, baseL + off);
            HMMA4(hh, ah[2 * kp],     bh[0], bh[1]);
            HMMA4(lh, al[2 * kp],     bh[0], bh[1]);
            HMMA4(hl, ah[2 * kp],     bl[0], bl[1]);
            HMMA4(hh, ah[2 * kp + 1], bh[2], bh[3]);
            HMMA4(lh, al[2 * kp + 1], bh[2], bh[3]);
            HMMA4(hl, ah[2 * kp + 1], bl[2], bl[3]);
        }
        int colloc = nb * 8 + 2 * (l & 3);
        int col = cb + colloc;
        float y0 = smYY[colloc], y1 = smYY[colloc + 1];
        if (col < CN) {
            out[(size_t)i0 * CN + col] = nx0 + (hh[0] + lh[0] + hl[0]) + y0;
            out[(size_t)i1 * CN + col] = nx1 + (hh[2] + lh[2] + hl[2]) + y0;
        }
        if (col + 1 < CN) {
            out[(size_t)i0 * CN + col + 1] = nx0 + (hh[1] + lh[1] + hl[1]) + y1;
            out[(size_t)i1 * CN + col + 1] = nx1 + (hh[3] + lh[3] + hl[3]) + y1;
        }
    }
}

// ---------------- CE + margin: one warp per row ------------------------------
__global__ void __launch_bounds__(256) ce_kernel(const float* __restrict__ nsd) {
    int w = threadIdx.x >> 5, l = threadIdx.x & 31;
    int i = blockIdx.x * 8 + w;
    int lab = g_lab[i];
    const float4* row = (const float4*)(nsd + (size_t)i * CN);

    float4 v[8];
    float m = -1e30f, vlab = -1e30f;
    #pragma unroll
    for (int k = 0; k < 8; k++) {
        int idx = l + 32 * k;
        float4 x = make_float4(-1e30f, -1e30f, -1e30f, -1e30f);
        if (idx < 250) {
            x = row[idx];
            int c0 = idx * 4;
            if (lab == c0)     { x.x *= 1.5f; vlab = x.x; }
            if (lab == c0 + 1) { x.y *= 1.5f; vlab = x.y; }
            if (lab == c0 + 2) { x.z *= 1.5f; vlab = x.z; }
            if (lab == c0 + 3) { x.w *= 1.5f; vlab = x.w; }
            m = fmaxf(m, fmaxf(fmaxf(x.x, x.y), fmaxf(x.z, x.w)));
        }
        v[k] = x;
    }
    #pragma unroll
    for (int d = 16; d; d >>= 1) {
        m = fmaxf(m, __shfl_xor_sync(0xffffffffu, m, d));
        vlab = fmaxf(vlab, __shfl_xor_sync(0xffffffffu, vlab, d));
    }
    float e = 0.f;
    #pragma unroll
    for (int k = 0; k < 8; k++)
        e += __expf(v[k].x - m) + __expf(v[k].y - m)
           + __expf(v[k].z - m) + __expf(v[k].w - m);
    #pragma unroll
    for (int d = 16; d; d >>= 1) e += __shfl_xor_sync(0xffffffffu, e, d);
    if (l == 0) g_ce[i] = -(vlab - m - logf(e));

    float4 f  = ((const float4*)(g_featn  + (size_t)i   * DN))[l];
    float4 mm = ((const float4*)(g_meansn + (size_t)lab * DN))[l];
    float dx = f.x - mm.x, dy = f.y - mm.y, dz = f.z - mm.z, dw = f.w - mm.w;
    float ms = dx * dx + dy * dy + dz * dz + dw * dw;
    #pragma unroll
    for (int d = 16; d; d >>= 1) ms += __shfl_xor_sync(0xffffffffu, ms, d);
    if (l == 0) g_margin[i] = ms;
}

// ---------------- SCL: mma.sync bf16 fused GEMM + row reduction --------------
// CTA = 256 i-rows x 128 j-cols; 8 warps x 32 rows -> 4 HMMA per B LDSM.x4
__global__ void __launch_bounds__(256, 2) scl_mma_kernel() {
    extern __shared__ __align__(16) char sm[];
    char* smT = sm;
    int* jl = (int*)(sm + TILE_BYTES);

    int tid = threadIdx.x;
    int w = tid >> 5;
    int l = tid & 31;
    int ib = blockIdx.x * 256;
    int split = blockIdx.y;

    uint32_t a[2][8][4];   // [strip 0/1][k-step][frag]

    // half 0 (rows ib..ib+127): warps 0-3 extract their 2 strips
    load_tile(smT, g_featbH, ib, tid);
    __syncthreads();
    if (w < 4) {
        uint32_t base = smem_u32(smT);
        load_a_frags16(base, 32 * w,      l, a[0]);
        load_a_frags16(base, 32 * w + 16, l, a[1]);
    }
    __syncthreads();
    // half 1 (rows ib+128..ib+255): warps 4-7 extract
    load_tile(smT, g_featbH, ib + 128, tid);
    __syncthreads();
    if (w >= 4) {
        uint32_t base = smem_u32(smT);
        load_a_frags16(base, 32 * (w - 4),      l, a[0]);
        load_a_frags16(base, 32 * (w - 4) + 16, l, a[1]);
    }
    // loop-top __syncthreads() covers extraction before B overwrites

    // this thread's 4 output rows (global)
    int ig[4], lab[4];
    {
        int base_r = ib + 32 * w + (l >> 2);
        ig[0] = base_r;      ig[1] = base_r + 8;
        ig[2] = base_r + 16; ig[3] = base_r + 24;
        #pragma unroll
        for (int q = 0; q < 4; q++) lab[q] = g_lab[ig[q]];
    }

    const float invT = 1.0f / 0.3f;
    float sB[4] = {0.f, 0.f, 0.f, 0.f};
    float sP[4] = {0.f, 0.f, 0.f, 0.f};
    int   sC[4] = {0, 0, 0, 0};

    uint32_t bbase = smem_u32(smT);
    uint32_t brow = (l & 7);
    uint32_t bkoff = 8 * (l >> 3);

    for (int jt = 0; jt < 64 / TSPLIT; jt++) {
        int jb = (split * (64 / TSPLIT) + jt) * 128;

        __syncthreads();   // previous tile (or A extraction) fully consumed
        load_tile(smT, g_featbH, jb, tid);
        if (tid < 128) jl[tid] = g_lab[jb + tid];
        __syncthreads();

        #pragma unroll
        for (int nb = 0; nb < 16; nb++) {
            // 4 independent chains: strip0/strip1 x even/odd k
            float e0[4] = {0.f, 0.f, 0.f, 0.f}, o0[4] = {0.f, 0.f, 0.f, 0.f};
            float e1[4] = {0.f, 0.f, 0.f, 0.f}, o1[4] = {0.f, 0.f, 0.f, 0.f};
            #pragma unroll
            for (int kp = 0; kp < 4; kp++) {
                uint32_t b[4];
                LDSM4(b, bbase + (nb * 8 + brow) * STRIDE + (32 * kp + bkoff) * 2);
                HMMA4(e0, a[0][2 * kp],     b[0], b[1]);
                HMMA4(e1, a[1][2 * kp],     b[0], b[1]);
                HMMA4(o0, a[0][2 * kp + 1], b[2], b[3]);
                HMMA4(o1, a[1][2 * kp + 1], b[2], b[3]);
            }
            int col = nb * 8 + 2 * (l & 3);
            int jg0 = jb + col, jg1 = jg0 + 1;
            int jl0 = jl[col], jl1 = jl[col + 1];

            float s0 = (e0[0] + o0[0]) * invT;   // (ig0, jg0)
            float s1 = (e0[1] + o0[1]) * invT;   // (ig0, jg1)
            float s2 = (e0[2] + o0[2]) * invT;   // (ig1, jg0)
            float s3 = (e0[3] + o0[3]) * invT;   // (ig1, jg1)
            float s4 = (e1[0] + o1[0]) * invT;   // (ig2, jg0)
            float s5 = (e1[1] + o1[1]) * invT;   // (ig2, jg1)
            float s6 = (e1[2] + o1[2]) * invT;   // (ig3, jg0)
            float s7 = (e1[3] + o1[3]) * invT;   // (ig3, jg1)

            if (jg0 != ig[0]) { sB[0] += __expf(s0); if (jl0 == lab[0]) { sP[0] += s0; sC[0]++; } }
            if (jg1 != ig[0]) { sB[0] += __expf(s1); if (jl1 == lab[0]) { sP[0] += s1; sC[0]++; } }
            if (jg0 != ig[1]) { sB[1] += __expf(s2); if (jl0 == lab[1]) { sP[1] += s2; sC[1]++; } }
            if (jg1 != ig[1]) { sB[1] += __expf(s3); if (jl1 == lab[1]) { sP[1] += s3; sC[1]++; } }
            if (jg0 != ig[2]) { sB[2] += __expf(s4); if (jl0 == lab[2]) { sP[2] += s4; sC[2]++; } }
            if (jg1 != ig[2]) { sB[2] += __expf(s5); if (jl1 == lab[2]) { sP[2] += s5; sC[2]++; } }
            if (jg0 != ig[3]) { sB[3] += __expf(s6); if (jl0 == lab[3]) { sP[3] += s6; sC[3]++; } }
            if (jg1 != ig[3]) { sB[3] += __expf(s7); if (jl1 == lab[3]) { sP[3] += s7; sC[3]++; } }
        }
    }

    // deterministic reduce across the 4 lanes sharing each row (width-4 segments)
    #pragma unroll
    for (int q = 0; q < 4; q++) {
        #pragma unroll
        for (int d = 2; d; d >>= 1) {
            sB[q] += __shfl_down_sync(0xffffffffu, sB[q], d, 4);
            sP[q] += __shfl_down_sync(0xffffffffu, sP[q], d, 4);
            sC[q] += __shfl_down_sync(0xffffffffu, sC[q], d, 4);
        }
    }
    if ((l & 3) == 0) {
        #pragma unroll
        for (int q = 0; q < 4; q++) {
            g_pb[split * BN + ig[q]] = sB[q];
            g_pp[split * BN + ig[q]] = sP[q];
            g_pc[split * BN + ig[q]] = sC[q];
        }
    }
}

// ---------------- combine + final --------------------------------------------
__global__ void combine_kernel() {
    int i = blockIdx.x * 256 + threadIdx.x;
    float b = 0.f, p = 0.f;
    int c = 0;
    #pragma unroll
    for (int s = 0; s < TSPLIT; s++) {
        b += g_pb[s * BN + i];
        p += g_pp[s * BN + i];
        c += g_pc[s * BN + i];
    }
    bool valid = (c > 0);
    g_peri[i]  = valid ? (p / (float)c - logf(b)) : 0.f;
    g_valid[i] = valid ? 1.f : 0.f;
}

__global__ void final_kernel(float* __restrict__ out, long long scalar_idx) {
    int t = threadIdx.x;
    float sp = 0.f, sv = 0.f, sc = 0.f, smg = 0.f;
    for (int i = t; i < BN; i += 256) {
        sp += g_peri[i];
        sv += g_valid[i];
        sc += g_ce[i];
        smg += g_margin[i];
    }
    __shared__ float r0[256], r1[256], r2[256], r3[256];
    r0[t] = sp; r1[t] = sv; r2[t] = sc; r3[t] = smg;
    __syncthreads();
    for (int d = 128; d; d >>= 1) {
        if (t < d) { r0[t] += r0[t+d]; r1[t] += r1[t+d]; r2[t] += r2[t+d]; r3[t] += r3[t+d]; }
        __syncthreads();
    }
    if (t == 0) {
        float scl = -r0[0] / fmaxf(r1[0], 1.f);
        float ce  = r2[0] / (float)BN;
        float lm  = r3[0] / (2.f * (float)BN);
        out[scalar_idx] = 0.9f * ce + 0.1f * scl + 0.5f * lm;
    }
}

// ---------------- launch ------------------------------------------------------
extern "C" void kernel_launch(void* const* d_in, const int* in_sizes, int n_in,
                              void* d_out, int out_size) {
    const float* feat   = (const float*)d_in[0];
    const int*   labels = (const int*)d_in[1];
    const float* means  = (const float*)d_in[2];
    float* out = (float*)d_out;

    static cudaStream_t sB = nullptr;
    static cudaEvent_t  eF = nullptr, eJ = nullptr;
    static int initTried = 0;
    if (!initTried) {
        initTried = 1;
        if (cudaStreamCreateWithFlags(&sB, cudaStreamNonBlocking) != cudaSuccess) sB = nullptr;
        if (sB) {
            if (cudaEventCreateWithFlags(&eF, cudaEventDisableTiming) != cudaSuccess) { eF = nullptr; }
            if (cudaEventCreateWithFlags(&eJ, cudaEventDisableTiming) != cudaSuccess) { eJ = nullptr; }
            if (!eF || !eJ) sB = nullptr;
        }
        cudaFuncSetAttribute(nsd_mma_kernel, cudaFuncAttributeMaxDynamicSharedMemorySize, SMEM_NSD);
        cudaFuncSetAttribute(scl_mma_kernel, cudaFuncAttributeMaxDynamicSharedMemorySize, SMEM_SCL);
    }
    bool fork = (sB != nullptr);

    prep_feat_kernel<<<BN / 8, dim3(32, 8)>>>(feat, labels);

    if (fork) {
        cudaEventRecord(eF, 0);
        cudaStreamWaitEvent(sB, eF, 0);
        scl_mma_kernel<<<dim3(BN / 256, TSPLIT), 256, SMEM_SCL, sB>>>();
        cudaEventRecord(eJ, sB);
    }

    prep_means_kernel<<<CPAD / 8, dim3(32, 8)>>>(means);
    nsd_mma_kernel<<<dim3(BN / 128, CPAD / 128), 256, SMEM_NSD>>>(out);
    ce_kernel<<<BN / 8, 256>>>(out);

    if (fork) {
        cudaStreamWaitEvent(0, eJ, 0);
    } else {
        scl_mma_kernel<<<dim3(BN / 256, TSPLIT), 256, SMEM_SCL>>>();
    }

    combine_kernel<<<BN / 256, 256>>>();
    final_kernel<<<1, 256>>>(out, (long long)out_size - 1);
}